// round 2
// baseline (speedup 1.0000x reference)
#include <cuda_runtime.h>
#include <math.h>

#define NMAX 50000
#define EMAX 800000
#define C 256

// ---------------- scratch (static device globals; no allocation) ----------------
__device__ float g_agg[(size_t)NMAX * C];   // mean-aggregated x  (51.2 MB)
__device__ float g_h[(size_t)NMAX * C];     // layer-1 output     (51.2 MB)
__device__ int   g_src[EMAX];
__device__ int   g_dst[EMAX];
__device__ int   g_cnt[NMAX];
__device__ int   g_rowstart[NMAX + 1];
__device__ int   g_cursor[NMAX];
__device__ int   g_csr[EMAX];
__device__ float g_pq[NMAX * 4];            // p0,p1,q0,q1 per node
__device__ int   g_is64;

// ---------------- dtype detection: int64 vs int32 edge_index ----------------
__global__ void detect_kernel(const unsigned* __restrict__ w) {
    __shared__ int nz;
    if (threadIdx.x == 0) nz = 0;
    __syncthreads();
    // If buffer is int64 (values < 2^31), every odd 32-bit word is 0.
    unsigned v = w[2 * threadIdx.x + 1];
    if (v != 0u) atomicAdd(&nz, 1);
    __syncthreads();
    if (threadIdx.x == 0) g_is64 = (nz == 0) ? 1 : 0;
}

// ---------------- convert + count (clamped, dtype-agnostic) ----------------
__global__ void zero_cnt_kernel(int n) {
    int i = blockIdx.x * blockDim.x + threadIdx.x;
    if (i < n) g_cnt[i] = 0;
}

__global__ void convert_count_kernel(const int* __restrict__ ei, int E, int n) {
    int e = blockIdx.x * blockDim.x + threadIdx.x;
    if (e >= E) return;
    int s, d;
    if (g_is64) {
        const long long* p = (const long long*)ei;
        s = (int)p[e];
        d = (int)p[(size_t)E + e];
    } else {
        s = ei[e];
        d = ei[E + e];
    }
    // clamp defensively: guarantees all later indexing is in-bounds
    if ((unsigned)s >= (unsigned)n) s = 0;
    if ((unsigned)d >= (unsigned)n) d = 0;
    g_src[e] = s;
    g_dst[e] = d;
    atomicAdd(&g_cnt[d], 1);
}

// ---------------- exclusive scan over counts ----------------
__global__ void scan_kernel(int n) {
    __shared__ int temp[1024];
    __shared__ int carry;
    if (threadIdx.x == 0) carry = 0;
    __syncthreads();
    for (int base = 0; base < n; base += 1024) {
        int i = base + threadIdx.x;
        int v = (i < n) ? g_cnt[i] : 0;
        temp[threadIdx.x] = v;
        __syncthreads();
        #pragma unroll
        for (int off = 1; off < 1024; off <<= 1) {
            int t = (threadIdx.x >= off) ? temp[threadIdx.x - off] : 0;
            __syncthreads();
            temp[threadIdx.x] += t;
            __syncthreads();
        }
        int excl = carry + temp[threadIdx.x] - v;
        if (i < n) { g_rowstart[i] = excl; g_cursor[i] = excl; }
        __syncthreads();
        if (threadIdx.x == 1023) carry += temp[1023];
        __syncthreads();
    }
    if (threadIdx.x == 0) g_rowstart[n] = carry;
}

__global__ void fill_kernel(int E) {
    int e = blockIdx.x * blockDim.x + threadIdx.x;
    if (e >= E) return;
    int pos = atomicAdd(&g_cursor[g_dst[e]], 1);
    g_csr[pos] = g_src[e];
}

// ---------------- layer-1 aggregation: warp per node, register accumulators ----------------
__global__ void agg1_kernel(const float* __restrict__ x, int n) {
    int w = (blockIdx.x * blockDim.x + threadIdx.x) >> 5;
    int lane = threadIdx.x & 31;
    if (w >= n) return;
    int s0 = g_rowstart[w], s1 = g_rowstart[w + 1];
    float4 a0 = make_float4(0.f, 0.f, 0.f, 0.f);
    float4 a1 = make_float4(0.f, 0.f, 0.f, 0.f);
    for (int e = s0; e < s1; e++) {
        int s = g_csr[e];
        const float4* row = (const float4*)(x + (size_t)s * C);
        float4 v0 = row[lane];
        float4 v1 = row[lane + 32];
        a0.x += v0.x; a0.y += v0.y; a0.z += v0.z; a0.w += v0.w;
        a1.x += v1.x; a1.y += v1.y; a1.z += v1.z; a1.w += v1.w;
    }
    float inv = (s1 > s0) ? 1.f / (float)(s1 - s0) : 0.f;
    a0.x *= inv; a0.y *= inv; a0.z *= inv; a0.w *= inv;
    a1.x *= inv; a1.y *= inv; a1.z *= inv; a1.w *= inv;
    float4* out = (float4*)(g_agg + (size_t)w * C);
    out[lane] = a0;
    out[lane + 32] = a1;
}

// ---------------- fused layer-1 GEMM: h = relu([agg|x] @ [W1l|W1r]^T + b1) ----------------
// M=n, N=256, K=512. Tiles: 128x128x16, 256 threads, 8x8 per thread.
__global__ __launch_bounds__(256, 2) void gemm1_kernel(
    const float* __restrict__ x, const float* __restrict__ W1l,
    const float* __restrict__ W1r, const float* __restrict__ b1, int M)
{
    __shared__ __align__(16) float As[16][132];
    __shared__ __align__(16) float Bs[16][132];
    int m0 = blockIdx.x * 128;
    int n0 = blockIdx.y * 128;
    int tid = threadIdx.x;
    int tn = tid & 15;      // 0..15 -> 8 cols each
    int tm = tid >> 4;      // 0..15 -> 8 rows each
    float c[8][8];
    #pragma unroll
    for (int i = 0; i < 8; i++)
        #pragma unroll
        for (int j = 0; j < 8; j++) c[i][j] = 0.f;

    for (int k0 = 0; k0 < 512; k0 += 16) {
        // A tile: 128 rows x 16 k, logical A = [g_agg | x] along K
        #pragma unroll
        for (int r = 0; r < 2; r++) {
            int idx = tid + r * 256;
            int mi = idx >> 2;
            int kq = (idx & 3) * 4;
            int m = m0 + mi;
            float4 v = make_float4(0.f, 0.f, 0.f, 0.f);
            if (m < M) {
                const float* base = (k0 < 256)
                    ? (g_agg + (size_t)m * C + k0 + kq)
                    : (x + (size_t)m * C + (k0 - 256) + kq);
                v = *(const float4*)base;
            }
            As[kq + 0][mi] = v.x; As[kq + 1][mi] = v.y;
            As[kq + 2][mi] = v.z; As[kq + 3][mi] = v.w;
        }
        // B tile: B(k,n) = W[n, k]  with W = [W1l | W1r] along K
        #pragma unroll
        for (int r = 0; r < 2; r++) {
            int idx = tid + r * 256;
            int ni = idx >> 2;
            int kq = (idx & 3) * 4;
            int nn = n0 + ni;
            const float* wb = (k0 < 256)
                ? (W1l + (size_t)nn * C + k0 + kq)
                : (W1r + (size_t)nn * C + (k0 - 256) + kq);
            float4 v = *(const float4*)wb;
            Bs[kq + 0][ni] = v.x; Bs[kq + 1][ni] = v.y;
            Bs[kq + 2][ni] = v.z; Bs[kq + 3][ni] = v.w;
        }
        __syncthreads();
        #pragma unroll
        for (int kk = 0; kk < 16; kk++) {
            float a[8], b[8];
            float4 t0 = *(const float4*)&As[kk][tm * 8];
            float4 t1 = *(const float4*)&As[kk][tm * 8 + 4];
            a[0] = t0.x; a[1] = t0.y; a[2] = t0.z; a[3] = t0.w;
            a[4] = t1.x; a[5] = t1.y; a[6] = t1.z; a[7] = t1.w;
            float4 u0 = *(const float4*)&Bs[kk][tn * 8];
            float4 u1 = *(const float4*)&Bs[kk][tn * 8 + 4];
            b[0] = u0.x; b[1] = u0.y; b[2] = u0.z; b[3] = u0.w;
            b[4] = u1.x; b[5] = u1.y; b[6] = u1.z; b[7] = u1.w;
            #pragma unroll
            for (int i = 0; i < 8; i++)
                #pragma unroll
                for (int j = 0; j < 8; j++)
                    c[i][j] = fmaf(a[i], b[j], c[i][j]);
        }
        __syncthreads();
    }
    // epilogue: +bias, relu, store h
    #pragma unroll
    for (int i = 0; i < 8; i++) {
        int m = m0 + tm * 8 + i;
        if (m < M) {
            #pragma unroll
            for (int j = 0; j < 8; j += 4) {
                int nn = n0 + tn * 8 + j;
                float4 o;
                o.x = fmaxf(c[i][j + 0] + b1[nn + 0], 0.f);
                o.y = fmaxf(c[i][j + 1] + b1[nn + 1], 0.f);
                o.z = fmaxf(c[i][j + 2] + b1[nn + 2], 0.f);
                o.w = fmaxf(c[i][j + 3] + b1[nn + 3], 0.f);
                *(float4*)&g_h[(size_t)m * C + nn] = o;
            }
        }
    }
}

// ---------------- layer-2 projection: p = h@W2l^T, q = h@W2r^T + b2 (warp per node) ----------------
__global__ void pq_kernel(const float* __restrict__ W2l, const float* __restrict__ W2r,
                          const float* __restrict__ b2, int n) {
    int w = (blockIdx.x * blockDim.x + threadIdx.x) >> 5;
    int lane = threadIdx.x & 31;
    if (w >= n) return;
    const float4* h = (const float4*)(g_h + (size_t)w * C);
    float4 h0 = h[lane];
    float4 h1 = h[lane + 32];
    float d0 = 0.f, d1 = 0.f, d2 = 0.f, d3 = 0.f;
    {
        float4 w0 = *(const float4*)(W2l + 4 * lane);
        float4 w1 = *(const float4*)(W2l + 128 + 4 * lane);
        d0 = h0.x * w0.x + h0.y * w0.y + h0.z * w0.z + h0.w * w0.w
           + h1.x * w1.x + h1.y * w1.y + h1.z * w1.z + h1.w * w1.w;
    }
    {
        float4 w0 = *(const float4*)(W2l + 256 + 4 * lane);
        float4 w1 = *(const float4*)(W2l + 384 + 4 * lane);
        d1 = h0.x * w0.x + h0.y * w0.y + h0.z * w0.z + h0.w * w0.w
           + h1.x * w1.x + h1.y * w1.y + h1.z * w1.z + h1.w * w1.w;
    }
    {
        float4 w0 = *(const float4*)(W2r + 4 * lane);
        float4 w1 = *(const float4*)(W2r + 128 + 4 * lane);
        d2 = h0.x * w0.x + h0.y * w0.y + h0.z * w0.z + h0.w * w0.w
           + h1.x * w1.x + h1.y * w1.y + h1.z * w1.z + h1.w * w1.w;
    }
    {
        float4 w0 = *(const float4*)(W2r + 256 + 4 * lane);
        float4 w1 = *(const float4*)(W2r + 384 + 4 * lane);
        d3 = h0.x * w0.x + h0.y * w0.y + h0.z * w0.z + h0.w * w0.w
           + h1.x * w1.x + h1.y * w1.y + h1.z * w1.z + h1.w * w1.w;
    }
    #pragma unroll
    for (int off = 16; off; off >>= 1) {
        d0 += __shfl_xor_sync(0xffffffffu, d0, off);
        d1 += __shfl_xor_sync(0xffffffffu, d1, off);
        d2 += __shfl_xor_sync(0xffffffffu, d2, off);
        d3 += __shfl_xor_sync(0xffffffffu, d3, off);
    }
    if (lane == 0) {
        g_pq[w * 4 + 0] = d0;
        g_pq[w * 4 + 1] = d1;
        g_pq[w * 4 + 2] = d2 + b2[0];
        g_pq[w * 4 + 3] = d3 + b2[1];
    }
}

// ---------------- layer-2 aggregation + log_softmax (thread per node) ----------------
__global__ void final_kernel(float* __restrict__ out, int n) {
    int i = blockIdx.x * blockDim.x + threadIdx.x;
    if (i >= n) return;
    int s0 = g_rowstart[i], s1 = g_rowstart[i + 1];
    float p0 = 0.f, p1 = 0.f;
    for (int e = s0; e < s1; e++) {
        int s = g_csr[e];
        p0 += g_pq[s * 4 + 0];
        p1 += g_pq[s * 4 + 1];
    }
    float inv = (s1 > s0) ? 1.f / (float)(s1 - s0) : 0.f;
    float o0 = p0 * inv + g_pq[i * 4 + 2];
    float o1 = p1 * inv + g_pq[i * 4 + 3];
    float m = fmaxf(o0, o1);
    float l = m + log1pf(expf(fminf(o0, o1) - m));
    out[i * 2 + 0] = o0 - l;
    out[i * 2 + 1] = o1 - l;
}

// ---------------- launcher ----------------
extern "C" void kernel_launch(void* const* d_in, const int* in_sizes, int n_in,
                              void* d_out, int out_size) {
    const float* x   = (const float*)d_in[0];
    const int*   ei  = (const int*)d_in[1];
    const float* W1l = (const float*)d_in[2];
    const float* b1  = (const float*)d_in[3];
    const float* W1r = (const float*)d_in[4];
    const float* W2l = (const float*)d_in[5];
    const float* b2  = (const float*)d_in[6];
    const float* W2r = (const float*)d_in[7];
    float* out = (float*)d_out;

    int n = in_sizes[0] / C;  if (n > NMAX) n = NMAX;
    int E = in_sizes[1] / 2;  if (E > EMAX) E = EMAX;

    detect_kernel<<<1, 256>>>((const unsigned*)ei);
    zero_cnt_kernel<<<(n + 255) / 256, 256>>>(n);
    convert_count_kernel<<<(E + 255) / 256, 256>>>(ei, E, n);
    scan_kernel<<<1, 1024>>>(n);
    fill_kernel<<<(E + 255) / 256, 256>>>(E);
    agg1_kernel<<<(n * 32 + 255) / 256, 256>>>(x, n);
    dim3 g1((n + 127) / 128, 2);
    gemm1_kernel<<<g1, 256>>>(x, W1l, W1r, b1, n);
    pq_kernel<<<(n * 32 + 255) / 256, 256>>>(W2l, W2r, b2, n);
    final_kernel<<<(n + 255) / 256, 256>>>(out, n);
}

// round 3
// speedup vs baseline: 1.1594x; 1.1594x over previous
#include <cuda_runtime.h>
#include <math.h>

#define NMAX 50000
#define EMAX 800000
#define C 256

typedef unsigned long long u64;

// ---------------- scratch (static device globals; no allocation) ----------------
__device__ float g_agg[(size_t)NMAX * C];   // mean-aggregated x  (51.2 MB)
__device__ float g_h[(size_t)NMAX * C];     // layer-1 output     (51.2 MB)
__device__ int   g_src[EMAX];
__device__ int   g_dst[EMAX];
__device__ int   g_cnt[NMAX];
__device__ int   g_rowstart[NMAX + 1];
__device__ int   g_cursor[NMAX];
__device__ int   g_csr[EMAX];
__device__ float g_pq[NMAX * 4];            // p0,p1,q0,q1 per node
__device__ int   g_is64;
__device__ int   g_blocksums[64];

// ---------------- f32x2 packed-FMA helpers (sm_100+) ----------------
__device__ __forceinline__ u64 pack2(float lo, float hi) {
    u64 r; asm("mov.b64 %0,{%1,%2};" : "=l"(r) : "f"(lo), "f"(hi)); return r;
}
__device__ __forceinline__ void unpack2(u64 v, float& lo, float& hi) {
    asm("mov.b64 {%0,%1},%2;" : "=f"(lo), "=f"(hi) : "l"(v));
}
__device__ __forceinline__ void ffma2(u64& d, u64 a, u64 b) {
    asm("fma.rn.f32x2 %0,%1,%2,%0;" : "+l"(d) : "l"(a), "l"(b));
}

// ---------------- dtype detection: int64 vs int32 edge_index ----------------
__global__ void detect_kernel(const unsigned* __restrict__ w) {
    __shared__ int nz;
    if (threadIdx.x == 0) nz = 0;
    __syncthreads();
    unsigned v = w[2 * threadIdx.x + 1];
    if (v != 0u) atomicAdd(&nz, 1);
    __syncthreads();
    if (threadIdx.x == 0) g_is64 = (nz == 0) ? 1 : 0;
}

__global__ void zero_cnt_kernel(int n) {
    int i = blockIdx.x * blockDim.x + threadIdx.x;
    if (i < n) g_cnt[i] = 0;
}

__global__ void convert_count_kernel(const int* __restrict__ ei, int E, int n) {
    int e = blockIdx.x * blockDim.x + threadIdx.x;
    if (e >= E) return;
    int s, d;
    if (g_is64) {
        const long long* p = (const long long*)ei;
        s = (int)p[e];
        d = (int)p[(size_t)E + e];
    } else {
        s = ei[e];
        d = ei[E + e];
    }
    if ((unsigned)s >= (unsigned)n) s = 0;
    if ((unsigned)d >= (unsigned)n) d = 0;
    g_src[e] = s;
    g_dst[e] = d;
    atomicAdd(&g_cnt[d], 1);
}

// ---------------- parallel exclusive scan (3 kernels) ----------------
__global__ void scan_block_kernel(int n) {        // grid = nb, block = 1024
    int i = blockIdx.x * 1024 + threadIdx.x;
    int v = (i < n) ? g_cnt[i] : 0;
    int lane = threadIdx.x & 31, wid = threadIdx.x >> 5;
    int x = v;
    #pragma unroll
    for (int off = 1; off < 32; off <<= 1) {
        int t = __shfl_up_sync(0xffffffffu, x, off);
        if (lane >= off) x += t;
    }
    __shared__ int wsum[32];
    if (lane == 31) wsum[wid] = x;
    __syncthreads();
    if (wid == 0) {
        int s = wsum[lane];
        #pragma unroll
        for (int off = 1; off < 32; off <<= 1) {
            int t = __shfl_up_sync(0xffffffffu, s, off);
            if (lane >= off) s += t;
        }
        wsum[lane] = s;
    }
    __syncthreads();
    int incl = x + (wid > 0 ? wsum[wid - 1] : 0);
    if (i < n) g_rowstart[i] = incl - v;          // block-local exclusive
    if (threadIdx.x == 1023) g_blocksums[blockIdx.x] = incl;  // block total
}

__global__ void scan_sums_kernel(int nb, int n) { // 1 block, 32 threads
    int t = threadIdx.x;
    int v0 = (2 * t < nb) ? g_blocksums[2 * t] : 0;
    int v1 = (2 * t + 1 < nb) ? g_blocksums[2 * t + 1] : 0;
    int s = v0 + v1;
    int x = s;
    #pragma unroll
    for (int off = 1; off < 32; off <<= 1) {
        int tt = __shfl_up_sync(0xffffffffu, x, off);
        if (t >= off) x += tt;
    }
    int excl = x - s;
    if (2 * t < nb) g_blocksums[2 * t] = excl;
    if (2 * t + 1 < nb) g_blocksums[2 * t + 1] = excl + v0;
    if (t == 31) g_rowstart[n] = x;               // grand total = E
}

__global__ void scan_add_kernel(int n) {          // grid = nb, block = 1024
    int i = blockIdx.x * 1024 + threadIdx.x;
    if (i < n) {
        int r = g_rowstart[i] + g_blocksums[blockIdx.x];
        g_rowstart[i] = r;
        g_cursor[i] = r;
    }
}

__global__ void fill_kernel(int E) {
    int e = blockIdx.x * blockDim.x + threadIdx.x;
    if (e >= E) return;
    int pos = atomicAdd(&g_cursor[g_dst[e]], 1);
    g_csr[pos] = g_src[e];
}

// ---------------- layer-1 aggregation: warp per node ----------------
__global__ void agg1_kernel(const float* __restrict__ x, int n) {
    int w = (blockIdx.x * blockDim.x + threadIdx.x) >> 5;
    int lane = threadIdx.x & 31;
    if (w >= n) return;
    int s0 = g_rowstart[w], s1 = g_rowstart[w + 1];
    float4 a0 = make_float4(0.f, 0.f, 0.f, 0.f);
    float4 a1 = make_float4(0.f, 0.f, 0.f, 0.f);
    for (int e = s0; e < s1; e++) {
        int s = g_csr[e];
        const float4* row = (const float4*)(x + (size_t)s * C);
        float4 v0 = row[lane];
        float4 v1 = row[lane + 32];
        a0.x += v0.x; a0.y += v0.y; a0.z += v0.z; a0.w += v0.w;
        a1.x += v1.x; a1.y += v1.y; a1.z += v1.z; a1.w += v1.w;
    }
    float inv = (s1 > s0) ? 1.f / (float)(s1 - s0) : 0.f;
    a0.x *= inv; a0.y *= inv; a0.z *= inv; a0.w *= inv;
    a1.x *= inv; a1.y *= inv; a1.z *= inv; a1.w *= inv;
    float4* out = (float4*)(g_agg + (size_t)w * C);
    out[lane] = a0;
    out[lane + 32] = a1;
}

// ---------------- fused layer-1 GEMM with packed f32x2 FMA ----------------
// h = relu([agg|x] @ [W1l|W1r]^T + b1). M=n, N=256, K=512.
// 128x128x16 tiles, 256 threads, 8x8 per thread (as 8x4 f32x2 pairs).
__global__ __launch_bounds__(256, 2) void gemm1_kernel(
    const float* __restrict__ x, const float* __restrict__ W1l,
    const float* __restrict__ W1r, const float* __restrict__ b1, int M)
{
    __shared__ __align__(16) float As[16][132];
    __shared__ __align__(16) float Bs[16][132];
    int m0 = blockIdx.x * 128;
    int n0 = blockIdx.y * 128;
    int tid = threadIdx.x;
    int tn = tid & 15;
    int tm = tid >> 4;
    u64 c2[8][4];
    #pragma unroll
    for (int i = 0; i < 8; i++)
        #pragma unroll
        for (int j = 0; j < 4; j++) c2[i][j] = 0ull;

    for (int k0 = 0; k0 < 512; k0 += 16) {
        #pragma unroll
        for (int r = 0; r < 2; r++) {
            int idx = tid + r * 256;
            int mi = idx >> 2;
            int kq = (idx & 3) * 4;
            int m = m0 + mi;
            float4 v = make_float4(0.f, 0.f, 0.f, 0.f);
            if (m < M) {
                const float* base = (k0 < 256)
                    ? (g_agg + (size_t)m * C + k0 + kq)
                    : (x + (size_t)m * C + (k0 - 256) + kq);
                v = *(const float4*)base;
            }
            As[kq + 0][mi] = v.x; As[kq + 1][mi] = v.y;
            As[kq + 2][mi] = v.z; As[kq + 3][mi] = v.w;
        }
        #pragma unroll
        for (int r = 0; r < 2; r++) {
            int idx = tid + r * 256;
            int ni = idx >> 2;
            int kq = (idx & 3) * 4;
            int nn = n0 + ni;
            const float* wb = (k0 < 256)
                ? (W1l + (size_t)nn * C + k0 + kq)
                : (W1r + (size_t)nn * C + (k0 - 256) + kq);
            float4 v = *(const float4*)wb;
            Bs[kq + 0][ni] = v.x; Bs[kq + 1][ni] = v.y;
            Bs[kq + 2][ni] = v.z; Bs[kq + 3][ni] = v.w;
        }
        __syncthreads();
        #pragma unroll
        for (int kk = 0; kk < 16; kk++) {
            float4 t0 = *(const float4*)&As[kk][tm * 8];
            float4 t1 = *(const float4*)&As[kk][tm * 8 + 4];
            float a[8] = {t0.x, t0.y, t0.z, t0.w, t1.x, t1.y, t1.z, t1.w};
            float4 u0 = *(const float4*)&Bs[kk][tn * 8];
            float4 u1 = *(const float4*)&Bs[kk][tn * 8 + 4];
            u64 bp[4];
            bp[0] = pack2(u0.x, u0.y); bp[1] = pack2(u0.z, u0.w);
            bp[2] = pack2(u1.x, u1.y); bp[3] = pack2(u1.z, u1.w);
            #pragma unroll
            for (int i = 0; i < 8; i++) {
                u64 ap = pack2(a[i], a[i]);
                #pragma unroll
                for (int j = 0; j < 4; j++) ffma2(c2[i][j], ap, bp[j]);
            }
        }
        __syncthreads();
    }
    // epilogue: +bias, relu, store h
    #pragma unroll
    for (int i = 0; i < 8; i++) {
        int m = m0 + tm * 8 + i;
        if (m < M) {
            #pragma unroll
            for (int j = 0; j < 4; j += 2) {
                int nn = n0 + tn * 8 + j * 2;
                float e0, e1, e2, e3;
                unpack2(c2[i][j], e0, e1);
                unpack2(c2[i][j + 1], e2, e3);
                float4 o;
                o.x = fmaxf(e0 + b1[nn + 0], 0.f);
                o.y = fmaxf(e1 + b1[nn + 1], 0.f);
                o.z = fmaxf(e2 + b1[nn + 2], 0.f);
                o.w = fmaxf(e3 + b1[nn + 3], 0.f);
                *(float4*)&g_h[(size_t)m * C + nn] = o;
            }
        }
    }
}

// ---------------- layer-2 projection: warp per node ----------------
__global__ void pq_kernel(const float* __restrict__ W2l, const float* __restrict__ W2r,
                          const float* __restrict__ b2, int n) {
    int w = (blockIdx.x * blockDim.x + threadIdx.x) >> 5;
    int lane = threadIdx.x & 31;
    if (w >= n) return;
    const float4* h = (const float4*)(g_h + (size_t)w * C);
    float4 h0 = h[lane];
    float4 h1 = h[lane + 32];
    float d0, d1, d2, d3;
    {
        float4 w0 = *(const float4*)(W2l + 4 * lane);
        float4 w1 = *(const float4*)(W2l + 128 + 4 * lane);
        d0 = h0.x * w0.x + h0.y * w0.y + h0.z * w0.z + h0.w * w0.w
           + h1.x * w1.x + h1.y * w1.y + h1.z * w1.z + h1.w * w1.w;
    }
    {
        float4 w0 = *(const float4*)(W2l + 256 + 4 * lane);
        float4 w1 = *(const float4*)(W2l + 384 + 4 * lane);
        d1 = h0.x * w0.x + h0.y * w0.y + h0.z * w0.z + h0.w * w0.w
           + h1.x * w1.x + h1.y * w1.y + h1.z * w1.z + h1.w * w1.w;
    }
    {
        float4 w0 = *(const float4*)(W2r + 4 * lane);
        float4 w1 = *(const float4*)(W2r + 128 + 4 * lane);
        d2 = h0.x * w0.x + h0.y * w0.y + h0.z * w0.z + h0.w * w0.w
           + h1.x * w1.x + h1.y * w1.y + h1.z * w1.z + h1.w * w1.w;
    }
    {
        float4 w0 = *(const float4*)(W2r + 256 + 4 * lane);
        float4 w1 = *(const float4*)(W2r + 384 + 4 * lane);
        d3 = h0.x * w0.x + h0.y * w0.y + h0.z * w0.z + h0.w * w0.w
           + h1.x * w1.x + h1.y * w1.y + h1.z * w1.z + h1.w * w1.w;
    }
    #pragma unroll
    for (int off = 16; off; off >>= 1) {
        d0 += __shfl_xor_sync(0xffffffffu, d0, off);
        d1 += __shfl_xor_sync(0xffffffffu, d1, off);
        d2 += __shfl_xor_sync(0xffffffffu, d2, off);
        d3 += __shfl_xor_sync(0xffffffffu, d3, off);
    }
    if (lane == 0) {
        g_pq[w * 4 + 0] = d0;
        g_pq[w * 4 + 1] = d1;
        g_pq[w * 4 + 2] = d2 + b2[0];
        g_pq[w * 4 + 3] = d3 + b2[1];
    }
}

// ---------------- layer-2 aggregation + log_softmax ----------------
__global__ void final_kernel(float* __restrict__ out, int n) {
    int i = blockIdx.x * blockDim.x + threadIdx.x;
    if (i >= n) return;
    int s0 = g_rowstart[i], s1 = g_rowstart[i + 1];
    float p0 = 0.f, p1 = 0.f;
    for (int e = s0; e < s1; e++) {
        int s = g_csr[e];
        p0 += g_pq[s * 4 + 0];
        p1 += g_pq[s * 4 + 1];
    }
    float inv = (s1 > s0) ? 1.f / (float)(s1 - s0) : 0.f;
    float o0 = p0 * inv + g_pq[i * 4 + 2];
    float o1 = p1 * inv + g_pq[i * 4 + 3];
    float m = fmaxf(o0, o1);
    float l = m + log1pf(expf(fminf(o0, o1) - m));
    out[i * 2 + 0] = o0 - l;
    out[i * 2 + 1] = o1 - l;
}

// ---------------- launcher ----------------
extern "C" void kernel_launch(void* const* d_in, const int* in_sizes, int n_in,
                              void* d_out, int out_size) {
    const float* x   = (const float*)d_in[0];
    const int*   ei  = (const int*)d_in[1];
    const float* W1l = (const float*)d_in[2];
    const float* b1  = (const float*)d_in[3];
    const float* W1r = (const float*)d_in[4];
    const float* W2l = (const float*)d_in[5];
    const float* b2  = (const float*)d_in[6];
    const float* W2r = (const float*)d_in[7];
    float* out = (float*)d_out;

    int n = in_sizes[0] / C;  if (n > NMAX) n = NMAX;
    int E = in_sizes[1] / 2;  if (E > EMAX) E = EMAX;
    int nb = (n + 1023) / 1024;

    detect_kernel<<<1, 256>>>((const unsigned*)ei);
    zero_cnt_kernel<<<(n + 255) / 256, 256>>>(n);
    convert_count_kernel<<<(E + 255) / 256, 256>>>(ei, E, n);
    scan_block_kernel<<<nb, 1024>>>(n);
    scan_sums_kernel<<<1, 32>>>(nb, n);
    scan_add_kernel<<<nb, 1024>>>(n);
    fill_kernel<<<(E + 255) / 256, 256>>>(E);
    agg1_kernel<<<(n * 32 + 255) / 256, 256>>>(x, n);
    dim3 g1((n + 127) / 128, 2);
    gemm1_kernel<<<g1, 256>>>(x, W1l, W1r, b1, n);
    pq_kernel<<<(n * 32 + 255) / 256, 256>>>(W2l, W2r, b2, n);
    final_kernel<<<(n + 255) / 256, 256>>>(out, n);
}

// round 5
// speedup vs baseline: 2.1282x; 1.8356x over previous
#include <cuda_runtime.h>
#include <cuda_bf16.h>
#include <math.h>

#define NMAX 50000
#define EMAX 800000
#define C 256

typedef unsigned long long u64;
typedef unsigned int u32;

// ---------------- scratch (static device globals; no allocation) ----------------
__device__ __align__(16) float g_agg[(size_t)NMAX * C];   // mean-aggregated x
__device__ int   g_src[EMAX];
__device__ int   g_dst[EMAX];
__device__ int   g_cnt[NMAX];
__device__ int   g_rowstart[NMAX + 1];
__device__ int   g_cursor[NMAX];
__device__ int   g_csr[EMAX];
__device__ __align__(16) float g_pq[NMAX * 4];
__device__ int   g_is64;
__device__ int   g_blocksums[64];
__device__ __align__(16) __nv_bfloat16 g_Whi[256 * 512];  // [W1l|W1r] bf16 hi
__device__ __align__(16) __nv_bfloat16 g_Wlo[256 * 512];  // bf16 lo
__device__ __align__(16) float4 g_W2pack[256];            // {W2l0,W2l1,W2r0,W2r1}[col]

__device__ __forceinline__ u32 packbf(float a, float b) {
    __nv_bfloat16 ha = __float2bfloat16(a), hb = __float2bfloat16(b);
    return (u32)__bfloat16_as_ushort(ha) | ((u32)__bfloat16_as_ushort(hb) << 16);
}
__device__ __forceinline__ float bfres(float v) {   // residual after bf16 rounding
    return v - __bfloat162float(__float2bfloat16(v));
}
__device__ __forceinline__ void mma16816(float* d, const u32* a, const u32* b) {
    asm volatile(
        "mma.sync.aligned.m16n8k16.row.col.f32.bf16.bf16.f32 "
        "{%0,%1,%2,%3}, {%4,%5,%6,%7}, {%8,%9}, {%0,%1,%2,%3};"
        : "+f"(d[0]), "+f"(d[1]), "+f"(d[2]), "+f"(d[3])
        : "r"(a[0]), "r"(a[1]), "r"(a[2]), "r"(a[3]), "r"(b[0]), "r"(b[1]));
}

// ---------------- dtype detection ----------------
__global__ void detect_kernel(const unsigned* __restrict__ w) {
    __shared__ int nz;
    if (threadIdx.x == 0) nz = 0;
    __syncthreads();
    unsigned v = w[2 * threadIdx.x + 1];
    if (v != 0u) atomicAdd(&nz, 1);
    __syncthreads();
    if (threadIdx.x == 0) g_is64 = (nz == 0) ? 1 : 0;
}

__global__ void zero_cnt_kernel(int n) {
    int i = blockIdx.x * blockDim.x + threadIdx.x;
    if (i < n) g_cnt[i] = 0;
}

__global__ void convert_count_kernel(const int* __restrict__ ei, int E, int n) {
    int e = blockIdx.x * blockDim.x + threadIdx.x;
    if (e >= E) return;
    int s, d;
    if (g_is64) {
        const long long* p = (const long long*)ei;
        s = (int)p[e];
        d = (int)p[(size_t)E + e];
    } else {
        s = ei[e];
        d = ei[E + e];
    }
    if ((unsigned)s >= (unsigned)n) s = 0;
    if ((unsigned)d >= (unsigned)n) d = 0;
    g_src[e] = s;
    g_dst[e] = d;
    atomicAdd(&g_cnt[d], 1);
}

// ---------------- parallel exclusive scan ----------------
__global__ void scan_block_kernel(int n) {
    int i = blockIdx.x * 1024 + threadIdx.x;
    int v = (i < n) ? g_cnt[i] : 0;
    int lane = threadIdx.x & 31, wid = threadIdx.x >> 5;
    int x = v;
    #pragma unroll
    for (int off = 1; off < 32; off <<= 1) {
        int t = __shfl_up_sync(0xffffffffu, x, off);
        if (lane >= off) x += t;
    }
    __shared__ int wsum[32];
    if (lane == 31) wsum[wid] = x;
    __syncthreads();
    if (wid == 0) {
        int s = wsum[lane];
        #pragma unroll
        for (int off = 1; off < 32; off <<= 1) {
            int t = __shfl_up_sync(0xffffffffu, s, off);
            if (lane >= off) s += t;
        }
        wsum[lane] = s;
    }
    __syncthreads();
    int incl = x + (wid > 0 ? wsum[wid - 1] : 0);
    if (i < n) g_rowstart[i] = incl - v;
    if (threadIdx.x == 1023) g_blocksums[blockIdx.x] = incl;
}

__global__ void scan_sums_kernel(int nb, int n) {
    int t = threadIdx.x;
    int v0 = (2 * t < nb) ? g_blocksums[2 * t] : 0;
    int v1 = (2 * t + 1 < nb) ? g_blocksums[2 * t + 1] : 0;
    int s = v0 + v1;
    int x = s;
    #pragma unroll
    for (int off = 1; off < 32; off <<= 1) {
        int tt = __shfl_up_sync(0xffffffffu, x, off);
        if (t >= off) x += tt;
    }
    int excl = x - s;
    if (2 * t < nb) g_blocksums[2 * t] = excl;
    if (2 * t + 1 < nb) g_blocksums[2 * t + 1] = excl + v0;
    if (t == 31) g_rowstart[n] = x;
}

__global__ void scan_add_kernel(int n) {
    int i = blockIdx.x * 1024 + threadIdx.x;
    if (i < n) {
        int r = g_rowstart[i] + g_blocksums[blockIdx.x];
        g_rowstart[i] = r;
        g_cursor[i] = r;
    }
}

__global__ void fill_kernel(int E) {
    int e = blockIdx.x * blockDim.x + threadIdx.x;
    if (e >= E) return;
    int pos = atomicAdd(&g_cursor[g_dst[e]], 1);
    g_csr[pos] = g_src[e];
}

// ---------------- weight pre-split to bf16 hi/lo + W2 packing ----------------
__global__ void wconv_kernel(const float* __restrict__ W1l, const float* __restrict__ W1r,
                             const float* __restrict__ W2l, const float* __restrict__ W2r) {
    int idx = blockIdx.x * 256 + threadIdx.x;   // 131072 total
    int nrow = idx >> 9;
    int k = idx & 511;
    float w = (k < 256) ? W1l[nrow * 256 + k] : W1r[nrow * 256 + (k - 256)];
    __nv_bfloat16 hi = __float2bfloat16(w);
    __nv_bfloat16 lo = __float2bfloat16(w - __bfloat162float(hi));
    g_Whi[idx] = hi;
    g_Wlo[idx] = lo;
    if (idx < 256)
        g_W2pack[idx] = make_float4(W2l[idx], W2l[256 + idx], W2r[idx], W2r[256 + idx]);
}

// ---------------- layer-1 aggregation: warp per node ----------------
__global__ void agg1_kernel(const float* __restrict__ x, int n) {
    int w = (blockIdx.x * blockDim.x + threadIdx.x) >> 5;
    int lane = threadIdx.x & 31;
    if (w >= n) return;
    int s0 = g_rowstart[w], s1 = g_rowstart[w + 1];
    float4 a0 = make_float4(0.f, 0.f, 0.f, 0.f);
    float4 a1 = make_float4(0.f, 0.f, 0.f, 0.f);
    for (int e = s0; e < s1; e++) {
        int s = g_csr[e];
        const float4* row = (const float4*)(x + (size_t)s * C);
        float4 v0 = row[lane];
        float4 v1 = row[lane + 32];
        a0.x += v0.x; a0.y += v0.y; a0.z += v0.z; a0.w += v0.w;
        a1.x += v1.x; a1.y += v1.y; a1.z += v1.z; a1.w += v1.w;
    }
    float inv = (s1 > s0) ? 1.f / (float)(s1 - s0) : 0.f;
    a0.x *= inv; a0.y *= inv; a0.z *= inv; a0.w *= inv;
    a1.x *= inv; a1.y *= inv; a1.z *= inv; a1.w *= inv;
    float4* out = (float4*)(g_agg + (size_t)w * C);
    out[lane] = a0;
    out[lane + 32] = a1;
}

// ---------------- mma.sync GEMM: h=relu([agg|x]@[W1l|W1r]^T+b1) + fused pq epilogue --
// CTA: 128 rows x 256 cols (full N), 512 threads, warp grid 4m x 4n, warp tile 32x64.
// bf16 split: D = Ah*Bh + Ah*Bl + Al*Bh, fp32 accum. K=512 in 16 tiles of 32.
#define PA 40                       // smem pitch in bf16 elems
#define SA_HI 0                     // 128*40*2 = 10240
#define SA_LO 10240
#define SB_HI 20480                 // 256*40*2 = 20480
#define SB_LO 40960
#define SW2   61440                 // 256 * 16 = 4096
#define SB1   65536                 // 1024
#define SMEMT 66560

__global__ void __launch_bounds__(512, 1) gemm_mma_kernel(
    const float* __restrict__ x, const float* __restrict__ b1,
    const float* __restrict__ b2, int M)
{
    extern __shared__ __align__(16) char smem[];
    int tid = threadIdx.x;
    int lane = tid & 31, wid = tid >> 5;
    int wm = wid >> 2, wn = wid & 3;
    int m0 = blockIdx.x * 128;

    float4* s_w2 = (float4*)(smem + SW2);
    float*  s_b1 = (float*)(smem + SB1);
    if (tid < 256) {
        s_w2[tid] = g_W2pack[tid];
        s_b1[tid] = b1[tid];
    }

    float c[2][8][4];
    #pragma unroll
    for (int mi = 0; mi < 2; mi++)
        #pragma unroll
        for (int ni = 0; ni < 8; ni++)
            #pragma unroll
            for (int j = 0; j < 4; j++) c[mi][ni][j] = 0.f;

    int ra = lane >> 2;            // 0..7
    int ka2 = (lane & 3) * 2;      // 0,2,4,6

    for (int kt = 0; kt < 16; kt++) {
        int kg = kt * 32;
        const float* asrc = (kg < 256) ? (const float*)g_agg : x;
        int kc = (kg < 256) ? kg : (kg - 256);
        __syncthreads();
        // ---- load A tile: 128 rows x 32 k, fp32 -> bf16 hi/lo
        #pragma unroll
        for (int i = 0; i < 2; i++) {
            int t = tid + i * 512;
            int r = t >> 3, f = t & 7;
            int m = m0 + r;
            float4 v = make_float4(0.f, 0.f, 0.f, 0.f);
            if (m < M) v = *(const float4*)(asrc + (size_t)m * C + kc + f * 4);
            uint2 h = make_uint2(packbf(v.x, v.y), packbf(v.z, v.w));
            uint2 l = make_uint2(packbf(bfres(v.x), bfres(v.y)),
                                 packbf(bfres(v.z), bfres(v.w)));
            int off = (r * PA + f * 4) * 2;
            *(uint2*)(smem + SA_HI + off) = h;
            *(uint2*)(smem + SA_LO + off) = l;
        }
        // ---- load B tile: 256 n-rows x 32 k (pre-split bf16)
        #pragma unroll
        for (int i = 0; i < 2; i++) {
            int t = tid + i * 512;
            int nr = t >> 2, g = t & 3;
            uint4 vh = *(const uint4*)(g_Whi + (size_t)nr * 512 + kg + g * 8);
            uint4 vl = *(const uint4*)(g_Wlo + (size_t)nr * 512 + kg + g * 8);
            int off = (nr * PA + g * 8) * 2;
            *(uint4*)(smem + SB_HI + off) = vh;
            *(uint4*)(smem + SB_LO + off) = vl;
        }
        __syncthreads();
        // ---- mma phase
        #pragma unroll
        for (int k16 = 0; k16 < 2; k16++) {
            int k0 = k16 * 16;
            u32 ah[2][4], al[2][4];
            #pragma unroll
            for (int mi = 0; mi < 2; mi++) {
                int base = ((32 * wm + 16 * mi + ra) * PA + k0 + ka2) * 2;
                ah[mi][0] = *(u32*)(smem + SA_HI + base);
                ah[mi][1] = *(u32*)(smem + SA_HI + base + 8 * PA * 2);
                ah[mi][2] = *(u32*)(smem + SA_HI + base + 16);
                ah[mi][3] = *(u32*)(smem + SA_HI + base + 8 * PA * 2 + 16);
                al[mi][0] = *(u32*)(smem + SA_LO + base);
                al[mi][1] = *(u32*)(smem + SA_LO + base + 8 * PA * 2);
                al[mi][2] = *(u32*)(smem + SA_LO + base + 16);
                al[mi][3] = *(u32*)(smem + SA_LO + base + 8 * PA * 2 + 16);
            }
            u32 bh[8][2], bl[8][2];
            #pragma unroll
            for (int ni = 0; ni < 8; ni++) {
                int nb = 64 * wn + 8 * ni + ra;
                int boff = (nb * PA + k0 + ka2) * 2;
                bh[ni][0] = *(u32*)(smem + SB_HI + boff);
                bh[ni][1] = *(u32*)(smem + SB_HI + boff + 16);
                bl[ni][0] = *(u32*)(smem + SB_LO + boff);
                bl[ni][1] = *(u32*)(smem + SB_LO + boff + 16);
            }
            #pragma unroll
            for (int mi = 0; mi < 2; mi++)
                #pragma unroll
                for (int ni = 0; ni < 8; ni++) {
                    mma16816(c[mi][ni], ah[mi], bh[ni]);
                    mma16816(c[mi][ni], ah[mi], bl[ni]);
                    mma16816(c[mi][ni], al[mi], bh[ni]);
                }
        }
    }
    __syncthreads();   // all mma smem reads done before s_part overwrites SA region

    // ---- epilogue: h = relu(acc + b1); partial p,q per row over this warp's 64 cols
    float pp[2][2][4];
    #pragma unroll
    for (int mi = 0; mi < 2; mi++)
        #pragma unroll
        for (int hh = 0; hh < 2; hh++)
            #pragma unroll
            for (int r = 0; r < 4; r++) pp[mi][hh][r] = 0.f;
    #pragma unroll
    for (int mi = 0; mi < 2; mi++)
        #pragma unroll
        for (int ni = 0; ni < 8; ni++)
            #pragma unroll
            for (int j = 0; j < 4; j++) {
                int col = 64 * wn + 8 * ni + ka2 + (j & 1);
                float h = fmaxf(c[mi][ni][j] + s_b1[col], 0.f);
                float4 wv = s_w2[col];
                int hh = j >> 1;
                pp[mi][hh][0] = fmaf(h, wv.x, pp[mi][hh][0]);
                pp[mi][hh][1] = fmaf(h, wv.y, pp[mi][hh][1]);
                pp[mi][hh][2] = fmaf(h, wv.z, pp[mi][hh][2]);
                pp[mi][hh][3] = fmaf(h, wv.w, pp[mi][hh][3]);
            }
    #pragma unroll
    for (int mi = 0; mi < 2; mi++)
        #pragma unroll
        for (int hh = 0; hh < 2; hh++)
            #pragma unroll
            for (int r = 0; r < 4; r++) {
                float v = pp[mi][hh][r];
                v += __shfl_xor_sync(0xffffffffu, v, 1);
                v += __shfl_xor_sync(0xffffffffu, v, 2);
                pp[mi][hh][r] = v;
            }
    float* s_part = (float*)smem;   // [4 wn][128 row][4]
    if ((lane & 3) == 0) {
        #pragma unroll
        for (int mi = 0; mi < 2; mi++)
            #pragma unroll
            for (int hh = 0; hh < 2; hh++) {
                int row = 32 * wm + 16 * mi + 8 * hh + ra;
                *(float4*)&s_part[(wn * 128 + row) * 4] =
                    make_float4(pp[mi][hh][0], pp[mi][hh][1], pp[mi][hh][2], pp[mi][hh][3]);
            }
    }
    __syncthreads();
    if (tid < 128) {
        int m = m0 + tid;
        if (m < M) {
            float4 s = make_float4(0.f, 0.f, 0.f, 0.f);
            #pragma unroll
            for (int w = 0; w < 4; w++) {
                float4 v = *(float4*)&s_part[(w * 128 + tid) * 4];
                s.x += v.x; s.y += v.y; s.z += v.z; s.w += v.w;
            }
            *(float4*)&g_pq[m * 4] = make_float4(s.x, s.y, s.z + b2[0], s.w + b2[1]);
        }
    }
}

// ---------------- layer-2 aggregation + log_softmax ----------------
__global__ void final_kernel(float* __restrict__ out, int n) {
    int i = blockIdx.x * blockDim.x + threadIdx.x;
    if (i >= n) return;
    int s0 = g_rowstart[i], s1 = g_rowstart[i + 1];
    float p0 = 0.f, p1 = 0.f;
    for (int e = s0; e < s1; e++) {
        int s = g_csr[e];
        p0 += g_pq[s * 4 + 0];
        p1 += g_pq[s * 4 + 1];
    }
    float inv = (s1 > s0) ? 1.f / (float)(s1 - s0) : 0.f;
    float o0 = p0 * inv + g_pq[i * 4 + 2];
    float o1 = p1 * inv + g_pq[i * 4 + 3];
    float m = fmaxf(o0, o1);
    float l = m + log1pf(expf(fminf(o0, o1) - m));
    out[i * 2 + 0] = o0 - l;
    out[i * 2 + 1] = o1 - l;
}

// ---------------- launcher ----------------
extern "C" void kernel_launch(void* const* d_in, const int* in_sizes, int n_in,
                              void* d_out, int out_size) {
    const float* x   = (const float*)d_in[0];
    const int*   ei  = (const int*)d_in[1];
    const float* W1l = (const float*)d_in[2];
    const float* b1  = (const float*)d_in[3];
    const float* W1r = (const float*)d_in[4];
    const float* W2l = (const float*)d_in[5];
    const float* b2  = (const float*)d_in[6];
    const float* W2r = (const float*)d_in[7];
    float* out = (float*)d_out;

    int n = in_sizes[0] / C;  if (n > NMAX) n = NMAX;
    int E = in_sizes[1] / 2;  if (E > EMAX) E = EMAX;
    int nb = (n + 1023) / 1024;

    cudaFuncSetAttribute(gemm_mma_kernel, cudaFuncAttributeMaxDynamicSharedMemorySize,
                         SMEMT);

    detect_kernel<<<1, 256>>>((const unsigned*)ei);
    zero_cnt_kernel<<<(n + 255) / 256, 256>>>(n);
    convert_count_kernel<<<(E + 255) / 256, 256>>>(ei, E, n);
    scan_block_kernel<<<nb, 1024>>>(n);
    scan_sums_kernel<<<1, 32>>>(nb, n);
    scan_add_kernel<<<nb, 1024>>>(n);
    fill_kernel<<<(E + 255) / 256, 256>>>(E);
    wconv_kernel<<<512, 256>>>(W1l, W1r, W2l, W2r);
    agg1_kernel<<<(n * 32 + 255) / 256, 256>>>(x, n);
    gemm_mma_kernel<<<(n + 127) / 128, 512, SMEMT>>>(x, b1, b2, n);
    final_kernel<<<(n + 255) / 256, 256>>>(out, n);
}

// round 6
// speedup vs baseline: 2.2080x; 1.0375x over previous
#include <cuda_runtime.h>
#include <cuda_bf16.h>
#include <math.h>

#define NMAX 50000
#define EMAX 800000
#define C 256

typedef unsigned long long u64;
typedef unsigned int u32;

// ---------------- scratch (static device globals; no allocation) ----------------
__device__ int   g_src[EMAX];
__device__ int   g_dst[EMAX];
__device__ int   g_cnt[NMAX];
__device__ int   g_rowstart[NMAX + 1];
__device__ int   g_cursor[NMAX];
__device__ int   g_csr[EMAX];
__device__ __align__(16) float g_pq[NMAX * 4];
__device__ int   g_is64;
__device__ int   g_blocksums[64];
__device__ __align__(16) __nv_bfloat16 g_Whi[256 * 512];   // [W1l|W1r] bf16 hi
__device__ __align__(16) __nv_bfloat16 g_Wlo[256 * 512];   // bf16 lo
__device__ __align__(16) float4 g_W2pack[256];             // {W2l0,W2l1,W2r0,W2r1}[col]
__device__ __align__(16) __nv_bfloat16 g_agghi[(size_t)NMAX * C];
__device__ __align__(16) __nv_bfloat16 g_agglo[(size_t)NMAX * C];
__device__ __align__(16) __nv_bfloat16 g_xhi[(size_t)NMAX * C];
__device__ __align__(16) __nv_bfloat16 g_xlo[(size_t)NMAX * C];

__device__ __forceinline__ u32 packbf(float a, float b) {
    __nv_bfloat16 ha = __float2bfloat16(a), hb = __float2bfloat16(b);
    return (u32)__bfloat16_as_ushort(ha) | ((u32)__bfloat16_as_ushort(hb) << 16);
}
__device__ __forceinline__ float bfres(float v) {
    return v - __bfloat162float(__float2bfloat16(v));
}
__device__ __forceinline__ void mma16816(float* d, const u32* a, const u32* b) {
    asm volatile(
        "mma.sync.aligned.m16n8k16.row.col.f32.bf16.bf16.f32 "
        "{%0,%1,%2,%3}, {%4,%5,%6,%7}, {%8,%9}, {%0,%1,%2,%3};"
        : "+f"(d[0]), "+f"(d[1]), "+f"(d[2]), "+f"(d[3])
        : "r"(a[0]), "r"(a[1]), "r"(a[2]), "r"(a[3]), "r"(b[0]), "r"(b[1]));
}
__device__ __forceinline__ u32 smem_u32(const void* p) {
    u32 a;
    asm("{ .reg .u64 t; cvta.to.shared.u64 t, %1; cvt.u32.u64 %0, t; }" : "=r"(a) : "l"(p));
    return a;
}
#define CP16(dst, src, sz) \
    asm volatile("cp.async.cg.shared.global [%0], [%1], 16, %2;" \
                 :: "r"(dst), "l"(src), "r"(sz))
#define CP_COMMIT() asm volatile("cp.async.commit_group;")
#define CP_WAIT(n)  asm volatile("cp.async.wait_group %0;" :: "n"(n))

// ---------------- dtype detection ----------------
__global__ void detect_kernel(const unsigned* __restrict__ w) {
    __shared__ int nz;
    if (threadIdx.x == 0) nz = 0;
    __syncthreads();
    unsigned v = w[2 * threadIdx.x + 1];
    if (v != 0u) atomicAdd(&nz, 1);
    __syncthreads();
    if (threadIdx.x == 0) g_is64 = (nz == 0) ? 1 : 0;
}

__global__ void zero_cnt_kernel(int n) {
    int i = blockIdx.x * blockDim.x + threadIdx.x;
    if (i < n) g_cnt[i] = 0;
}

__global__ void convert_count_kernel(const int* __restrict__ ei, int E, int n) {
    int e = blockIdx.x * blockDim.x + threadIdx.x;
    if (e >= E) return;
    int s, d;
    if (g_is64) {
        const long long* p = (const long long*)ei;
        s = (int)p[e];
        d = (int)p[(size_t)E + e];
    } else {
        s = ei[e];
        d = ei[E + e];
    }
    if ((unsigned)s >= (unsigned)n) s = 0;
    if ((unsigned)d >= (unsigned)n) d = 0;
    g_src[e] = s;
    g_dst[e] = d;
    atomicAdd(&g_cnt[d], 1);
}

// ---------------- parallel exclusive scan ----------------
__global__ void scan_block_kernel(int n) {
    int i = blockIdx.x * 1024 + threadIdx.x;
    int v = (i < n) ? g_cnt[i] : 0;
    int lane = threadIdx.x & 31, wid = threadIdx.x >> 5;
    int x = v;
    #pragma unroll
    for (int off = 1; off < 32; off <<= 1) {
        int t = __shfl_up_sync(0xffffffffu, x, off);
        if (lane >= off) x += t;
    }
    __shared__ int wsum[32];
    if (lane == 31) wsum[wid] = x;
    __syncthreads();
    if (wid == 0) {
        int s = wsum[lane];
        #pragma unroll
        for (int off = 1; off < 32; off <<= 1) {
            int t = __shfl_up_sync(0xffffffffu, s, off);
            if (lane >= off) s += t;
        }
        wsum[lane] = s;
    }
    __syncthreads();
    int incl = x + (wid > 0 ? wsum[wid - 1] : 0);
    if (i < n) g_rowstart[i] = incl - v;
    if (threadIdx.x == 1023) g_blocksums[blockIdx.x] = incl;
}

__global__ void scan_sums_kernel(int nb, int n) {
    int t = threadIdx.x;
    int v0 = (2 * t < nb) ? g_blocksums[2 * t] : 0;
    int v1 = (2 * t + 1 < nb) ? g_blocksums[2 * t + 1] : 0;
    int s = v0 + v1;
    int x = s;
    #pragma unroll
    for (int off = 1; off < 32; off <<= 1) {
        int tt = __shfl_up_sync(0xffffffffu, x, off);
        if (t >= off) x += tt;
    }
    int excl = x - s;
    if (2 * t < nb) g_blocksums[2 * t] = excl;
    if (2 * t + 1 < nb) g_blocksums[2 * t + 1] = excl + v0;
    if (t == 31) g_rowstart[n] = x;
}

__global__ void scan_add_kernel(int n) {
    int i = blockIdx.x * 1024 + threadIdx.x;
    if (i < n) {
        int r = g_rowstart[i] + g_blocksums[blockIdx.x];
        g_rowstart[i] = r;
        g_cursor[i] = r;
    }
}

__global__ void fill_kernel(int E) {
    int e = blockIdx.x * blockDim.x + threadIdx.x;
    if (e >= E) return;
    int pos = atomicAdd(&g_cursor[g_dst[e]], 1);
    g_csr[pos] = g_src[e];
}

// ---------------- weight pre-split + W2 packing ----------------
__global__ void wconv_kernel(const float* __restrict__ W1l, const float* __restrict__ W1r,
                             const float* __restrict__ W2l, const float* __restrict__ W2r) {
    int idx = blockIdx.x * 256 + threadIdx.x;   // 131072 total
    int nrow = idx >> 9;
    int k = idx & 511;
    float w = (k < 256) ? W1l[nrow * 256 + k] : W1r[nrow * 256 + (k - 256)];
    __nv_bfloat16 hi = __float2bfloat16(w);
    __nv_bfloat16 lo = __float2bfloat16(w - __bfloat162float(hi));
    g_Whi[idx] = hi;
    g_Wlo[idx] = lo;
    if (idx < 256)
        g_W2pack[idx] = make_float4(W2l[idx], W2l[256 + idx], W2r[idx], W2r[256 + idx]);
}

// ---------------- x pre-split to bf16 hi/lo ----------------
__global__ void xsplit_kernel(const float* __restrict__ x, int n) {
    int idx = blockIdx.x * 256 + threadIdx.x;   // n*64 float4 groups
    if (idx >= n * 64) return;
    float4 v = *(const float4*)(x + (size_t)idx * 4);
    uint2 h = make_uint2(packbf(v.x, v.y), packbf(v.z, v.w));
    uint2 l = make_uint2(packbf(bfres(v.x), bfres(v.y)), packbf(bfres(v.z), bfres(v.w)));
    *(uint2*)(g_xhi + (size_t)idx * 4) = h;
    *(uint2*)(g_xlo + (size_t)idx * 4) = l;
}

// ---------------- layer-1 aggregation: warp per node, writes bf16 hi/lo ----------------
__global__ void agg1_kernel(const float* __restrict__ x, int n) {
    int w = (blockIdx.x * blockDim.x + threadIdx.x) >> 5;
    int lane = threadIdx.x & 31;
    if (w >= n) return;
    int s0 = g_rowstart[w], s1 = g_rowstart[w + 1];
    float4 a0 = make_float4(0.f, 0.f, 0.f, 0.f);
    float4 a1 = make_float4(0.f, 0.f, 0.f, 0.f);
    for (int e = s0; e < s1; e++) {
        int s = g_csr[e];
        const float4* row = (const float4*)(x + (size_t)s * C);
        float4 v0 = row[lane];
        float4 v1 = row[lane + 32];
        a0.x += v0.x; a0.y += v0.y; a0.z += v0.z; a0.w += v0.w;
        a1.x += v1.x; a1.y += v1.y; a1.z += v1.z; a1.w += v1.w;
    }
    float inv = (s1 > s0) ? 1.f / (float)(s1 - s0) : 0.f;
    a0.x *= inv; a0.y *= inv; a0.z *= inv; a0.w *= inv;
    a1.x *= inv; a1.y *= inv; a1.z *= inv; a1.w *= inv;
    size_t base = (size_t)w * C;
    *(uint2*)(g_agghi + base + 4 * lane) = make_uint2(packbf(a0.x, a0.y), packbf(a0.z, a0.w));
    *(uint2*)(g_agglo + base + 4 * lane) =
        make_uint2(packbf(bfres(a0.x), bfres(a0.y)), packbf(bfres(a0.z), bfres(a0.w)));
    *(uint2*)(g_agghi + base + 128 + 4 * lane) = make_uint2(packbf(a1.x, a1.y), packbf(a1.z, a1.w));
    *(uint2*)(g_agglo + base + 128 + 4 * lane) =
        make_uint2(packbf(bfres(a1.x), bfres(a1.y)), packbf(bfres(a1.z), bfres(a1.w)));
}

// ---------------- double-buffered mma.sync GEMM + fused pq epilogue ----------------
// CTA: 128 rows x 256 cols, 512 threads, warp grid 4m x 4n, warp tile 32x64.
// D = Ah*Bh + Ah*Bl + Al*Bh, fp32 accum. K=512 in 16 tiles of 32. 2-stage cp.async.
#define PA 40                        // smem pitch in bf16 (80 bytes, 16B-aligned)
#define SA_HI 0                      // 128*80 = 10240
#define SA_LO 10240
#define SB_HI 20480                  // 256*80 = 20480
#define SB_LO 40960
#define STAGE 61440
#define SW2   122880                 // 256*16 = 4096
#define SB1   126976                 // 1024
#define SMEMT 128000

__global__ void __launch_bounds__(512, 1) gemm_mma_kernel(
    const float* __restrict__ b1, const float* __restrict__ b2, int M)
{
    extern __shared__ __align__(16) char smem[];
    u32 sb = smem_u32(smem);
    int tid = threadIdx.x;
    int lane = tid & 31, wid = tid >> 5;
    int wm = wid >> 2, wn = wid & 3;
    int m0 = blockIdx.x * 128;

    float4* s_w2 = (float4*)(smem + SW2);
    float*  s_b1 = (float*)(smem + SB1);
    if (tid < 256) {
        s_w2[tid] = g_W2pack[tid];
        s_b1[tid] = b1[tid];
    }

    // per-thread cp.async assignments
    int arow = tid >> 2, ach = tid & 3;          // A: 512 chunks of 16B per buf
    int am = m0 + arow;
    u32 asz = (am < M) ? 16u : 0u;
    u32 a_soff = (u32)(arow * 80 + ach * 16);
    size_t a_goff = (size_t)am * C + ach * 8;    // + k offset per tile

    auto issue = [&](int kt, int st) {
        u32 s0 = sb + st * STAGE;
        const __nv_bfloat16 *ah, *al;
        size_t ago;
        if (kt < 8) { ah = g_agghi; al = g_agglo; ago = a_goff + kt * 32; }
        else        { ah = g_xhi;   al = g_xlo;   ago = a_goff + kt * 32 - 256; }
        CP16(s0 + SA_HI + a_soff, ah + ago, asz);
        CP16(s0 + SA_LO + a_soff, al + ago, asz);
        int kg = kt * 32;
        #pragma unroll
        for (int i = 0; i < 2; i++) {
            int t = tid + i * 512;
            int nr = t >> 2, ch = t & 3;
            u32 boff = (u32)(nr * 80 + ch * 16);
            size_t bgo = (size_t)nr * 512 + kg + ch * 8;
            CP16(s0 + SB_HI + boff, g_Whi + bgo, 16u);
            CP16(s0 + SB_LO + boff, g_Wlo + bgo, 16u);
        }
        CP_COMMIT();
    };

    float c[2][8][4];
    #pragma unroll
    for (int mi = 0; mi < 2; mi++)
        #pragma unroll
        for (int ni = 0; ni < 8; ni++)
            #pragma unroll
            for (int j = 0; j < 4; j++) c[mi][ni][j] = 0.f;

    int ra = lane >> 2;
    int ka2 = (lane & 3) * 2;

    issue(0, 0);
    for (int kt = 0; kt < 16; kt++) {
        if (kt < 15) { issue(kt + 1, (kt + 1) & 1); CP_WAIT(1); }
        else         { CP_WAIT(0); }
        __syncthreads();
        char* sB = smem + (kt & 1) * STAGE;
        #pragma unroll
        for (int k16 = 0; k16 < 2; k16++) {
            int k0 = k16 * 16;
            u32 ah[2][4], al[2][4];
            #pragma unroll
            for (int mi = 0; mi < 2; mi++) {
                int base = ((32 * wm + 16 * mi + ra) * PA + k0 + ka2) * 2;
                ah[mi][0] = *(u32*)(sB + SA_HI + base);
                ah[mi][1] = *(u32*)(sB + SA_HI + base + 8 * PA * 2);
                ah[mi][2] = *(u32*)(sB + SA_HI + base + 16);
                ah[mi][3] = *(u32*)(sB + SA_HI + base + 8 * PA * 2 + 16);
                al[mi][0] = *(u32*)(sB + SA_LO + base);
                al[mi][1] = *(u32*)(sB + SA_LO + base + 8 * PA * 2);
                al[mi][2] = *(u32*)(sB + SA_LO + base + 16);
                al[mi][3] = *(u32*)(sB + SA_LO + base + 8 * PA * 2 + 16);
            }
            u32 bh[8][2], bl[8][2];
            #pragma unroll
            for (int ni = 0; ni < 8; ni++) {
                int nb = 64 * wn + 8 * ni + ra;
                int boff = (nb * PA + k0 + ka2) * 2;
                bh[ni][0] = *(u32*)(sB + SB_HI + boff);
                bh[ni][1] = *(u32*)(sB + SB_HI + boff + 16);
                bl[ni][0] = *(u32*)(sB + SB_LO + boff);
                bl[ni][1] = *(u32*)(sB + SB_LO + boff + 16);
            }
            #pragma unroll
            for (int mi = 0; mi < 2; mi++)
                #pragma unroll
                for (int ni = 0; ni < 8; ni++) {
                    mma16816(c[mi][ni], ah[mi], bh[ni]);
                    mma16816(c[mi][ni], ah[mi], bl[ni]);
                    mma16816(c[mi][ni], al[mi], bh[ni]);
                }
        }
        __syncthreads();
    }

    // ---- epilogue: h = relu(acc + b1); fused p,q projection
    float pp[2][2][4];
    #pragma unroll
    for (int mi = 0; mi < 2; mi++)
        #pragma unroll
        for (int hh = 0; hh < 2; hh++)
            #pragma unroll
            for (int r = 0; r < 4; r++) pp[mi][hh][r] = 0.f;
    #pragma unroll
    for (int mi = 0; mi < 2; mi++)
        #pragma unroll
        for (int ni = 0; ni < 8; ni++)
            #pragma unroll
            for (int j = 0; j < 4; j++) {
                int col = 64 * wn + 8 * ni + ka2 + (j & 1);
                float h = fmaxf(c[mi][ni][j] + s_b1[col], 0.f);
                float4 wv = s_w2[col];
                int hh = j >> 1;
                pp[mi][hh][0] = fmaf(h, wv.x, pp[mi][hh][0]);
                pp[mi][hh][1] = fmaf(h, wv.y, pp[mi][hh][1]);
                pp[mi][hh][2] = fmaf(h, wv.z, pp[mi][hh][2]);
                pp[mi][hh][3] = fmaf(h, wv.w, pp[mi][hh][3]);
            }
    #pragma unroll
    for (int mi = 0; mi < 2; mi++)
        #pragma unroll
        for (int hh = 0; hh < 2; hh++)
            #pragma unroll
            for (int r = 0; r < 4; r++) {
                float v = pp[mi][hh][r];
                v += __shfl_xor_sync(0xffffffffu, v, 1);
                v += __shfl_xor_sync(0xffffffffu, v, 2);
                pp[mi][hh][r] = v;
            }
    float* s_part = (float*)smem;   // [4 wn][128 row][4]
    if ((lane & 3) == 0) {
        #pragma unroll
        for (int mi = 0; mi < 2; mi++)
            #pragma unroll
            for (int hh = 0; hh < 2; hh++) {
                int row = 32 * wm + 16 * mi + 8 * hh + ra;
                *(float4*)&s_part[(wn * 128 + row) * 4] =
                    make_float4(pp[mi][hh][0], pp[mi][hh][1], pp[mi][hh][2], pp[mi][hh][3]);
            }
    }
    __syncthreads();
    if (tid < 128) {
        int m = m0 + tid;
        if (m < M) {
            float4 s = make_float4(0.f, 0.f, 0.f, 0.f);
            #pragma unroll
            for (int w = 0; w < 4; w++) {
                float4 v = *(float4*)&s_part[(w * 128 + tid) * 4];
                s.x += v.x; s.y += v.y; s.z += v.z; s.w += v.w;
            }
            *(float4*)&g_pq[m * 4] = make_float4(s.x, s.y, s.z + b2[0], s.w + b2[1]);
        }
    }
}

// ---------------- layer-2 aggregation + log_softmax ----------------
__global__ void final_kernel(float* __restrict__ out, int n) {
    int i = blockIdx.x * blockDim.x + threadIdx.x;
    if (i >= n) return;
    int s0 = g_rowstart[i], s1 = g_rowstart[i + 1];
    float p0 = 0.f, p1 = 0.f;
    for (int e = s0; e < s1; e++) {
        int s = g_csr[e];
        p0 += g_pq[s * 4 + 0];
        p1 += g_pq[s * 4 + 1];
    }
    float inv = (s1 > s0) ? 1.f / (float)(s1 - s0) : 0.f;
    float o0 = p0 * inv + g_pq[i * 4 + 2];
    float o1 = p1 * inv + g_pq[i * 4 + 3];
    float m = fmaxf(o0, o1);
    float l = m + log1pf(expf(fminf(o0, o1) - m));
    out[i * 2 + 0] = o0 - l;
    out[i * 2 + 1] = o1 - l;
}

// ---------------- launcher ----------------
extern "C" void kernel_launch(void* const* d_in, const int* in_sizes, int n_in,
                              void* d_out, int out_size) {
    const float* x   = (const float*)d_in[0];
    const int*   ei  = (const int*)d_in[1];
    const float* W1l = (const float*)d_in[2];
    const float* b1  = (const float*)d_in[3];
    const float* W1r = (const float*)d_in[4];
    const float* W2l = (const float*)d_in[5];
    const float* b2  = (const float*)d_in[6];
    const float* W2r = (const float*)d_in[7];
    float* out = (float*)d_out;

    int n = in_sizes[0] / C;  if (n > NMAX) n = NMAX;
    int E = in_sizes[1] / 2;  if (E > EMAX) E = EMAX;
    int nb = (n + 1023) / 1024;

    cudaFuncSetAttribute(gemm_mma_kernel, cudaFuncAttributeMaxDynamicSharedMemorySize,
                         SMEMT);

    detect_kernel<<<1, 256>>>((const unsigned*)ei);
    zero_cnt_kernel<<<(n + 255) / 256, 256>>>(n);
    convert_count_kernel<<<(E + 255) / 256, 256>>>(ei, E, n);
    scan_block_kernel<<<nb, 1024>>>(n);
    scan_sums_kernel<<<1, 32>>>(nb, n);
    scan_add_kernel<<<nb, 1024>>>(n);
    fill_kernel<<<(E + 255) / 256, 256>>>(E);
    wconv_kernel<<<512, 256>>>(W1l, W1r, W2l, W2r);
    xsplit_kernel<<<(n * 64 + 255) / 256, 256>>>(x, n);
    agg1_kernel<<<(n * 32 + 255) / 256, 256>>>(x, n);
    gemm_mma_kernel<<<(n + 127) / 128, 512, SMEMT>>>(b1, b2, n);
    final_kernel<<<(n + 255) / 256, 256>>>(out, n);
}

// round 7
// speedup vs baseline: 2.3470x; 1.0630x over previous
#include <cuda_runtime.h>
#include <cuda_bf16.h>
#include <cuda_fp16.h>
#include <math.h>

#define NMAX 50000
#define EMAX 800000
#define C 256

typedef unsigned long long u64;
typedef unsigned int u32;

// ---------------- scratch (static device globals; no allocation) ----------------
__device__ int   g_src[EMAX];
__device__ int   g_dst[EMAX];
__device__ int   g_cnt[NMAX];
__device__ int   g_rowstart[NMAX + 1];
__device__ int   g_cursor[NMAX];
__device__ int   g_csr[EMAX];
__device__ __align__(16) float g_pq[NMAX * 4];
__device__ int   g_is64;
__device__ int   g_blocksums[64];
__device__ __align__(16) __nv_bfloat16 g_Whi[256 * 512];   // [W1l|W1r] bf16 hi
__device__ __align__(16) __nv_bfloat16 g_Wlo[256 * 512];   // bf16 lo
__device__ __align__(16) float4 g_W2pack[256];             // {W2l0,W2l1,W2r0,W2r1}[col]
__device__ __align__(16) __nv_bfloat16 g_agghi[(size_t)NMAX * C];
__device__ __align__(16) __nv_bfloat16 g_agglo[(size_t)NMAX * C];
__device__ __align__(16) __nv_bfloat16 g_xhi[(size_t)NMAX * C];
__device__ __align__(16) __nv_bfloat16 g_xlo[(size_t)NMAX * C];
__device__ __align__(16) __half g_xhalf[(size_t)NMAX * C];  // fp16 x for gather

__device__ __forceinline__ u32 packbf(float a, float b) {
    __nv_bfloat16 ha = __float2bfloat16(a), hb = __float2bfloat16(b);
    return (u32)__bfloat16_as_ushort(ha) | ((u32)__bfloat16_as_ushort(hb) << 16);
}
__device__ __forceinline__ u32 packhf(float a, float b) {
    __half2 h = __floats2half2_rn(a, b);
    return *(u32*)&h;
}
__device__ __forceinline__ float bfres(float v) {
    return v - __bfloat162float(__float2bfloat16(v));
}
__device__ __forceinline__ void mma16816(float* d, const u32* a, const u32* b) {
    asm volatile(
        "mma.sync.aligned.m16n8k16.row.col.f32.bf16.bf16.f32 "
        "{%0,%1,%2,%3}, {%4,%5,%6,%7}, {%8,%9}, {%0,%1,%2,%3};"
        : "+f"(d[0]), "+f"(d[1]), "+f"(d[2]), "+f"(d[3])
        : "r"(a[0]), "r"(a[1]), "r"(a[2]), "r"(a[3]), "r"(b[0]), "r"(b[1]));
}
__device__ __forceinline__ u32 smem_u32(const void* p) {
    u32 a;
    asm("{ .reg .u64 t; cvta.to.shared.u64 t, %1; cvt.u32.u64 %0, t; }" : "=r"(a) : "l"(p));
    return a;
}
#define CP16(dst, src, sz) \
    asm volatile("cp.async.cg.shared.global [%0], [%1], 16, %2;" \
                 :: "r"(dst), "l"(src), "r"(sz))
#define CP_COMMIT() asm volatile("cp.async.commit_group;")
#define CP_WAIT(n)  asm volatile("cp.async.wait_group %0;" :: "n"(n))

// ---------------- init: zero counts + dtype detection (merged) ----------------
__global__ void init_kernel(const unsigned* __restrict__ w, int n) {
    int i = blockIdx.x * blockDim.x + threadIdx.x;
    if (i < n) g_cnt[i] = 0;
    if (blockIdx.x == 0) {
        __shared__ int nz;
        if (threadIdx.x == 0) nz = 0;
        __syncthreads();
        if (w[2 * threadIdx.x + 1] != 0u) atomicAdd(&nz, 1);
        __syncthreads();
        if (threadIdx.x == 0) g_is64 = (nz == 0) ? 1 : 0;
    }
}

__global__ void convert_count_kernel(const int* __restrict__ ei, int E, int n) {
    int e = blockIdx.x * blockDim.x + threadIdx.x;
    if (e >= E) return;
    int s, d;
    if (g_is64) {
        const long long* p = (const long long*)ei;
        s = (int)p[e];
        d = (int)p[(size_t)E + e];
    } else {
        s = ei[e];
        d = ei[E + e];
    }
    if ((unsigned)s >= (unsigned)n) s = 0;
    if ((unsigned)d >= (unsigned)n) d = 0;
    g_src[e] = s;
    g_dst[e] = d;
    atomicAdd(&g_cnt[d], 1);
}

// ---------------- parallel exclusive scan (2 kernels) ----------------
__global__ void scan_block_kernel(int n) {
    int i = blockIdx.x * 1024 + threadIdx.x;
    int v = (i < n) ? g_cnt[i] : 0;
    int lane = threadIdx.x & 31, wid = threadIdx.x >> 5;
    int x = v;
    #pragma unroll
    for (int off = 1; off < 32; off <<= 1) {
        int t = __shfl_up_sync(0xffffffffu, x, off);
        if (lane >= off) x += t;
    }
    __shared__ int wsum[32];
    if (lane == 31) wsum[wid] = x;
    __syncthreads();
    if (wid == 0) {
        int s = wsum[lane];
        #pragma unroll
        for (int off = 1; off < 32; off <<= 1) {
            int t = __shfl_up_sync(0xffffffffu, s, off);
            if (lane >= off) s += t;
        }
        wsum[lane] = s;
    }
    __syncthreads();
    int incl = x + (wid > 0 ? wsum[wid - 1] : 0);
    if (i < n) g_rowstart[i] = incl - v;
    if (threadIdx.x == 1023) g_blocksums[blockIdx.x] = incl;
}

__global__ void scan_add_kernel(int n, int nb) {
    __shared__ int s_off;
    int b = blockIdx.x;
    if (threadIdx.x < 32) {
        int lane = threadIdx.x;
        int v = 0;
        if (lane < nb && lane < b) v += g_blocksums[lane];
        int l2 = lane + 32;
        if (l2 < nb && l2 < b) v += g_blocksums[l2];
        #pragma unroll
        for (int off = 16; off; off >>= 1)
            v += __shfl_xor_sync(0xffffffffu, v, off);
        if (lane == 0) s_off = v;
    }
    __syncthreads();
    int i = b * 1024 + threadIdx.x;
    if (i < n) {
        int r = g_rowstart[i] + s_off;
        g_rowstart[i] = r;
        g_cursor[i] = r;
    }
    if (b == nb - 1 && threadIdx.x == 0)
        g_rowstart[n] = s_off + g_blocksums[b];
}

__global__ void fill_kernel(int E) {
    int e = blockIdx.x * blockDim.x + threadIdx.x;
    if (e >= E) return;
    int pos = atomicAdd(&g_cursor[g_dst[e]], 1);
    g_csr[pos] = g_src[e];
}

// ---------------- weight pre-split + W2 packing ----------------
__global__ void wconv_kernel(const float* __restrict__ W1l, const float* __restrict__ W1r,
                             const float* __restrict__ W2l, const float* __restrict__ W2r) {
    int idx = blockIdx.x * 256 + threadIdx.x;   // 131072 total
    int nrow = idx >> 9;
    int k = idx & 511;
    float w = (k < 256) ? W1l[nrow * 256 + k] : W1r[nrow * 256 + (k - 256)];
    __nv_bfloat16 hi = __float2bfloat16(w);
    __nv_bfloat16 lo = __float2bfloat16(w - __bfloat162float(hi));
    g_Whi[idx] = hi;
    g_Wlo[idx] = lo;
    if (idx < 256)
        g_W2pack[idx] = make_float4(W2l[idx], W2l[256 + idx], W2r[idx], W2r[256 + idx]);
}

// ---------------- x pre-split to bf16 hi/lo + fp16 copy ----------------
__global__ void xsplit_kernel(const float* __restrict__ x, int n) {
    int idx = blockIdx.x * 256 + threadIdx.x;   // n*64 float4 groups
    if (idx >= n * 64) return;
    float4 v = *(const float4*)(x + (size_t)idx * 4);
    uint2 h = make_uint2(packbf(v.x, v.y), packbf(v.z, v.w));
    uint2 l = make_uint2(packbf(bfres(v.x), bfres(v.y)), packbf(bfres(v.z), bfres(v.w)));
    *(uint2*)(g_xhi + (size_t)idx * 4) = h;
    *(uint2*)(g_xlo + (size_t)idx * 4) = l;
    *(uint2*)(g_xhalf + (size_t)idx * 4) = make_uint2(packhf(v.x, v.y), packhf(v.z, v.w));
}

// ---------------- layer-1 aggregation: warp per node, fp16 gather ----------------
__global__ void agg1_kernel(int n) {
    int w = (blockIdx.x * blockDim.x + threadIdx.x) >> 5;
    int lane = threadIdx.x & 31;
    if (w >= n) return;
    int s0 = g_rowstart[w], s1 = g_rowstart[w + 1];
    float f0 = 0.f, f1 = 0.f, f2 = 0.f, f3 = 0.f;
    float f4 = 0.f, f5 = 0.f, f6 = 0.f, f7 = 0.f;
    for (int e = s0; e < s1; e++) {
        int s = g_csr[e];
        uint4 v = *(const uint4*)(g_xhalf + (size_t)s * C + 8 * lane);
        float2 p0 = __half22float2(*(__half2*)&v.x);
        float2 p1 = __half22float2(*(__half2*)&v.y);
        float2 p2 = __half22float2(*(__half2*)&v.z);
        float2 p3 = __half22float2(*(__half2*)&v.w);
        f0 += p0.x; f1 += p0.y; f2 += p1.x; f3 += p1.y;
        f4 += p2.x; f5 += p2.y; f6 += p3.x; f7 += p3.y;
    }
    float inv = (s1 > s0) ? 1.f / (float)(s1 - s0) : 0.f;
    f0 *= inv; f1 *= inv; f2 *= inv; f3 *= inv;
    f4 *= inv; f5 *= inv; f6 *= inv; f7 *= inv;
    size_t base = (size_t)w * C + 8 * lane;
    uint4 hi = make_uint4(packbf(f0, f1), packbf(f2, f3), packbf(f4, f5), packbf(f6, f7));
    uint4 lo = make_uint4(packbf(bfres(f0), bfres(f1)), packbf(bfres(f2), bfres(f3)),
                          packbf(bfres(f4), bfres(f5)), packbf(bfres(f6), bfres(f7)));
    *(uint4*)(g_agghi + base) = hi;
    *(uint4*)(g_agglo + base) = lo;
}

// ---------------- double-buffered mma.sync GEMM + fused pq epilogue ----------------
// CTA: 128 rows x 256 cols, 512 threads, warp grid 4m x 4n, warp tile 32x64.
// D = Ah*Bh + Ah*Bl + Al*Bh, fp32 accum. K=512 in 16 tiles of 32. 2-stage cp.async.
#define PA 40                        // smem pitch in bf16 (80 bytes, 16B-aligned)
#define SA_HI 0                      // 128*80 = 10240
#define SA_LO 10240
#define SB_HI 20480                  // 256*80 = 20480
#define SB_LO 40960
#define STAGE 61440
#define SW2   122880                 // 256*16 = 4096
#define SB1   126976                 // 1024
#define SMEMT 128000

__global__ void __launch_bounds__(512, 1) gemm_mma_kernel(
    const float* __restrict__ b1, const float* __restrict__ b2, int M)
{
    extern __shared__ __align__(16) char smem[];
    u32 sb = smem_u32(smem);
    int tid = threadIdx.x;
    int lane = tid & 31, wid = tid >> 5;
    int wm = wid >> 2, wn = wid & 3;
    int m0 = blockIdx.x * 128;

    float4* s_w2 = (float4*)(smem + SW2);
    float*  s_b1 = (float*)(smem + SB1);
    if (tid < 256) {
        s_w2[tid] = g_W2pack[tid];
        s_b1[tid] = b1[tid];
    }

    // per-thread cp.async assignments
    int arow = tid >> 2, ach = tid & 3;          // A: 512 chunks of 16B per buf
    int am = m0 + arow;
    u32 asz = (am < M) ? 16u : 0u;
    u32 a_soff = (u32)(arow * 80 + ach * 16);
    size_t a_goff = (size_t)am * C + ach * 8;    // + k offset per tile

    auto issue = [&](int kt, int st) {
        u32 s0 = sb + st * STAGE;
        const __nv_bfloat16 *ah, *al;
        size_t ago;
        if (kt < 8) { ah = g_agghi; al = g_agglo; ago = a_goff + kt * 32; }
        else        { ah = g_xhi;   al = g_xlo;   ago = a_goff + kt * 32 - 256; }
        CP16(s0 + SA_HI + a_soff, ah + ago, asz);
        CP16(s0 + SA_LO + a_soff, al + ago, asz);
        int kg = kt * 32;
        #pragma unroll
        for (int i = 0; i < 2; i++) {
            int t = tid + i * 512;
            int nr = t >> 2, ch = t & 3;
            u32 boff = (u32)(nr * 80 + ch * 16);
            size_t bgo = (size_t)nr * 512 + kg + ch * 8;
            CP16(s0 + SB_HI + boff, g_Whi + bgo, 16u);
            CP16(s0 + SB_LO + boff, g_Wlo + bgo, 16u);
        }
        CP_COMMIT();
    };

    float c[2][8][4];
    #pragma unroll
    for (int mi = 0; mi < 2; mi++)
        #pragma unroll
        for (int ni = 0; ni < 8; ni++)
            #pragma unroll
            for (int j = 0; j < 4; j++) c[mi][ni][j] = 0.f;

    int ra = lane >> 2;
    int ka2 = (lane & 3) * 2;

    issue(0, 0);
    for (int kt = 0; kt < 16; kt++) {
        if (kt < 15) { issue(kt + 1, (kt + 1) & 1); CP_WAIT(1); }
        else         { CP_WAIT(0); }
        __syncthreads();
        char* sB = smem + (kt & 1) * STAGE;
        #pragma unroll
        for (int k16 = 0; k16 < 2; k16++) {
            int k0 = k16 * 16;
            u32 ah[2][4], al[2][4];
            #pragma unroll
            for (int mi = 0; mi < 2; mi++) {
                int base = ((32 * wm + 16 * mi + ra) * PA + k0 + ka2) * 2;
                ah[mi][0] = *(u32*)(sB + SA_HI + base);
                ah[mi][1] = *(u32*)(sB + SA_HI + base + 8 * PA * 2);
                ah[mi][2] = *(u32*)(sB + SA_HI + base + 16);
                ah[mi][3] = *(u32*)(sB + SA_HI + base + 8 * PA * 2 + 16);
                al[mi][0] = *(u32*)(sB + SA_LO + base);
                al[mi][1] = *(u32*)(sB + SA_LO + base + 8 * PA * 2);
                al[mi][2] = *(u32*)(sB + SA_LO + base + 16);
                al[mi][3] = *(u32*)(sB + SA_LO + base + 8 * PA * 2 + 16);
            }
            u32 bh[8][2], bl[8][2];
            #pragma unroll
            for (int ni = 0; ni < 8; ni++) {
                int nb = 64 * wn + 8 * ni + ra;
                int boff = (nb * PA + k0 + ka2) * 2;
                bh[ni][0] = *(u32*)(sB + SB_HI + boff);
                bh[ni][1] = *(u32*)(sB + SB_HI + boff + 16);
                bl[ni][0] = *(u32*)(sB + SB_LO + boff);
                bl[ni][1] = *(u32*)(sB + SB_LO + boff + 16);
            }
            #pragma unroll
            for (int mi = 0; mi < 2; mi++)
                #pragma unroll
                for (int ni = 0; ni < 8; ni++) {
                    mma16816(c[mi][ni], ah[mi], bh[ni]);
                    mma16816(c[mi][ni], ah[mi], bl[ni]);
                    mma16816(c[mi][ni], al[mi], bh[ni]);
                }
        }
        __syncthreads();
    }

    // ---- epilogue: h = relu(acc + b1); fused p,q projection
    float pp[2][2][4];
    #pragma unroll
    for (int mi = 0; mi < 2; mi++)
        #pragma unroll
        for (int hh = 0; hh < 2; hh++)
            #pragma unroll
            for (int r = 0; r < 4; r++) pp[mi][hh][r] = 0.f;
    #pragma unroll
    for (int mi = 0; mi < 2; mi++)
        #pragma unroll
        for (int ni = 0; ni < 8; ni++)
            #pragma unroll
            for (int j = 0; j < 4; j++) {
                int col = 64 * wn + 8 * ni + ka2 + (j & 1);
                float h = fmaxf(c[mi][ni][j] + s_b1[col], 0.f);
                float4 wv = s_w2[col];
                int hh = j >> 1;
                pp[mi][hh][0] = fmaf(h, wv.x, pp[mi][hh][0]);
                pp[mi][hh][1] = fmaf(h, wv.y, pp[mi][hh][1]);
                pp[mi][hh][2] = fmaf(h, wv.z, pp[mi][hh][2]);
                pp[mi][hh][3] = fmaf(h, wv.w, pp[mi][hh][3]);
            }
    #pragma unroll
    for (int mi = 0; mi < 2; mi++)
        #pragma unroll
        for (int hh = 0; hh < 2; hh++)
            #pragma unroll
            for (int r = 0; r < 4; r++) {
                float v = pp[mi][hh][r];
                v += __shfl_xor_sync(0xffffffffu, v, 1);
                v += __shfl_xor_sync(0xffffffffu, v, 2);
                pp[mi][hh][r] = v;
            }
    float* s_part = (float*)smem;   // [4 wn][128 row][4]
    if ((lane & 3) == 0) {
        #pragma unroll
        for (int mi = 0; mi < 2; mi++)
            #pragma unroll
            for (int hh = 0; hh < 2; hh++) {
                int row = 32 * wm + 16 * mi + 8 * hh + ra;
                *(float4*)&s_part[(wn * 128 + row) * 4] =
                    make_float4(pp[mi][hh][0], pp[mi][hh][1], pp[mi][hh][2], pp[mi][hh][3]);
            }
    }
    __syncthreads();
    if (tid < 128) {
        int m = m0 + tid;
        if (m < M) {
            float4 s = make_float4(0.f, 0.f, 0.f, 0.f);
            #pragma unroll
            for (int w = 0; w < 4; w++) {
                float4 v = *(float4*)&s_part[(w * 128 + tid) * 4];
                s.x += v.x; s.y += v.y; s.z += v.z; s.w += v.w;
            }
            *(float4*)&g_pq[m * 4] = make_float4(s.x, s.y, s.z + b2[0], s.w + b2[1]);
        }
    }
}

// ---------------- layer-2 aggregation + log_softmax ----------------
__global__ void final_kernel(float* __restrict__ out, int n) {
    int i = blockIdx.x * blockDim.x + threadIdx.x;
    if (i >= n) return;
    int s0 = g_rowstart[i], s1 = g_rowstart[i + 1];
    float p0 = 0.f, p1 = 0.f;
    for (int e = s0; e < s1; e++) {
        int s = g_csr[e];
        p0 += g_pq[s * 4 + 0];
        p1 += g_pq[s * 4 + 1];
    }
    float inv = (s1 > s0) ? 1.f / (float)(s1 - s0) : 0.f;
    float o0 = p0 * inv + g_pq[i * 4 + 2];
    float o1 = p1 * inv + g_pq[i * 4 + 3];
    float m = fmaxf(o0, o1);
    float l = m + log1pf(expf(fminf(o0, o1) - m));
    out[i * 2 + 0] = o0 - l;
    out[i * 2 + 1] = o1 - l;
}

// ---------------- launcher ----------------
extern "C" void kernel_launch(void* const* d_in, const int* in_sizes, int n_in,
                              void* d_out, int out_size) {
    const float* x   = (const float*)d_in[0];
    const int*   ei  = (const int*)d_in[1];
    const float* W1l = (const float*)d_in[2];
    const float* b1  = (const float*)d_in[3];
    const float* W1r = (const float*)d_in[4];
    const float* W2l = (const float*)d_in[5];
    const float* b2  = (const float*)d_in[6];
    const float* W2r = (const float*)d_in[7];
    float* out = (float*)d_out;

    int n = in_sizes[0] / C;  if (n > NMAX) n = NMAX;
    int E = in_sizes[1] / 2;  if (E > EMAX) E = EMAX;
    int nb = (n + 1023) / 1024;

    cudaFuncSetAttribute(gemm_mma_kernel, cudaFuncAttributeMaxDynamicSharedMemorySize,
                         SMEMT);

    init_kernel<<<(n + 255) / 256, 256>>>((const unsigned*)ei, n);
    convert_count_kernel<<<(E + 255) / 256, 256>>>(ei, E, n);
    scan_block_kernel<<<nb, 1024>>>(n);
    scan_add_kernel<<<nb, 1024>>>(n, nb);
    fill_kernel<<<(E + 255) / 256, 256>>>(E);
    wconv_kernel<<<512, 256>>>(W1l, W1r, W2l, W2r);
    xsplit_kernel<<<(n * 64 + 255) / 256, 256>>>(x, n);
    agg1_kernel<<<(n * 32 + 255) / 256, 256>>>(n);
    gemm_mma_kernel<<<(n + 127) / 128, 512, SMEMT>>>(b1, b2, n);
    final_kernel<<<(n + 255) / 256, 256>>>(out, n);
}

// round 8
// speedup vs baseline: 2.9011x; 1.2361x over previous
#include <cuda_runtime.h>
#include <cuda_fp16.h>
#include <math.h>

#define NMAX 50000
#define EMAX 800000
#define C 256

typedef unsigned long long u64;
typedef unsigned int u32;

// ---------------- scratch (static device globals; no allocation) ----------------
__device__ int   g_src[EMAX];
__device__ int   g_dst[EMAX];
__device__ int   g_cnt[NMAX];
__device__ int   g_rowstart[NMAX + 1];
__device__ int   g_cursor[NMAX];
__device__ int   g_csr[EMAX];
__device__ __align__(16) float g_pq[NMAX * 4];
__device__ int   g_is64;
__device__ int   g_blocksums[64];
__device__ __align__(16) __half g_Whi[256 * 512];          // [W1l|W1r] fp16 hi
__device__ __align__(16) __half g_Wlo[256 * 512];          // fp16 lo (residual)
__device__ __align__(16) float4 g_W2pack[256];             // {W2l0,W2l1,W2r0,W2r1}[col]
__device__ __align__(16) __half g_agghalf[(size_t)NMAX * C];
__device__ __align__(16) __half g_xhalf[(size_t)NMAX * C];

__device__ __forceinline__ u32 packhf(float a, float b) {
    __half2 h = __floats2half2_rn(a, b);
    return *(u32*)&h;
}
__device__ __forceinline__ void mma16816(float* d, const u32* a, const u32* b) {
    asm volatile(
        "mma.sync.aligned.m16n8k16.row.col.f32.f16.f16.f32 "
        "{%0,%1,%2,%3}, {%4,%5,%6,%7}, {%8,%9}, {%0,%1,%2,%3};"
        : "+f"(d[0]), "+f"(d[1]), "+f"(d[2]), "+f"(d[3])
        : "r"(a[0]), "r"(a[1]), "r"(a[2]), "r"(a[3]), "r"(b[0]), "r"(b[1]));
}
__device__ __forceinline__ u32 smem_u32(const void* p) {
    u32 a;
    asm("{ .reg .u64 t; cvta.to.shared.u64 t, %1; cvt.u32.u64 %0, t; }" : "=r"(a) : "l"(p));
    return a;
}
#define CP16(dst, src, sz) \
    asm volatile("cp.async.cg.shared.global [%0], [%1], 16, %2;" \
                 :: "r"(dst), "l"(src), "r"(sz))
#define CP_COMMIT() asm volatile("cp.async.commit_group;")
#define CP_WAIT(n)  asm volatile("cp.async.wait_group %0;" :: "n"(n))

// ---------------- init: zero counts + dtype detection ----------------
__global__ void init_kernel(const unsigned* __restrict__ w, int n) {
    int i = blockIdx.x * blockDim.x + threadIdx.x;
    if (i < n) g_cnt[i] = 0;
    if (blockIdx.x == 0) {
        __shared__ int nz;
        if (threadIdx.x == 0) nz = 0;
        __syncthreads();
        if (w[2 * threadIdx.x + 1] != 0u) atomicAdd(&nz, 1);
        __syncthreads();
        if (threadIdx.x == 0) g_is64 = (nz == 0) ? 1 : 0;
    }
}

// ---------------- merged prep: xsplit | convert_count | wconv ----------------
__global__ void prep_kernel(const float* __restrict__ x, const int* __restrict__ ei,
                            const float* __restrict__ W1l, const float* __restrict__ W1r,
                            const float* __restrict__ W2l, const float* __restrict__ W2r,
                            int n, int E, int nbx, int nbc) {
    int b = blockIdx.x;
    int tid = threadIdx.x;
    if (b < nbx) {
        // x -> fp16 copy
        int idx = b * 256 + tid;
        if (idx < n * 64) {
            float4 v = *(const float4*)(x + (size_t)idx * 4);
            *(uint2*)(g_xhalf + (size_t)idx * 4) =
                make_uint2(packhf(v.x, v.y), packhf(v.z, v.w));
        }
    } else if (b < nbx + nbc) {
        // edge convert + degree count
        int e = (b - nbx) * 256 + tid;
        if (e < E) {
            int s, d;
            if (g_is64) {
                const long long* p = (const long long*)ei;
                s = (int)p[e];
                d = (int)p[(size_t)E + e];
            } else {
                s = ei[e];
                d = ei[E + e];
            }
            if ((unsigned)s >= (unsigned)n) s = 0;
            if ((unsigned)d >= (unsigned)n) d = 0;
            g_src[e] = s;
            g_dst[e] = d;
            atomicAdd(&g_cnt[d], 1);
        }
    } else {
        // weight fp16 hi/lo split + W2 packing
        int idx = (b - nbx - nbc) * 256 + tid;   // < 131072
        int nrow = idx >> 9;
        int k = idx & 511;
        float w = (k < 256) ? W1l[nrow * 256 + k] : W1r[nrow * 256 + (k - 256)];
        __half hi = __float2half_rn(w);
        __half lo = __float2half_rn(w - __half2float(hi));
        g_Whi[idx] = hi;
        g_Wlo[idx] = lo;
        if (idx < 256)
            g_W2pack[idx] = make_float4(W2l[idx], W2l[256 + idx], W2r[idx], W2r[256 + idx]);
    }
}

// ---------------- parallel exclusive scan (2 kernels) ----------------
__global__ void scan_block_kernel(int n) {
    int i = blockIdx.x * 1024 + threadIdx.x;
    int v = (i < n) ? g_cnt[i] : 0;
    int lane = threadIdx.x & 31, wid = threadIdx.x >> 5;
    int x = v;
    #pragma unroll
    for (int off = 1; off < 32; off <<= 1) {
        int t = __shfl_up_sync(0xffffffffu, x, off);
        if (lane >= off) x += t;
    }
    __shared__ int wsum[32];
    if (lane == 31) wsum[wid] = x;
    __syncthreads();
    if (wid == 0) {
        int s = wsum[lane];
        #pragma unroll
        for (int off = 1; off < 32; off <<= 1) {
            int t = __shfl_up_sync(0xffffffffu, s, off);
            if (lane >= off) s += t;
        }
        wsum[lane] = s;
    }
    __syncthreads();
    int incl = x + (wid > 0 ? wsum[wid - 1] : 0);
    if (i < n) g_rowstart[i] = incl - v;
    if (threadIdx.x == 1023) g_blocksums[blockIdx.x] = incl;
}

__global__ void scan_add_kernel(int n, int nb) {
    __shared__ int s_off;
    int b = blockIdx.x;
    if (threadIdx.x < 32) {
        int lane = threadIdx.x;
        int v = 0;
        if (lane < nb && lane < b) v += g_blocksums[lane];
        int l2 = lane + 32;
        if (l2 < nb && l2 < b) v += g_blocksums[l2];
        #pragma unroll
        for (int off = 16; off; off >>= 1)
            v += __shfl_xor_sync(0xffffffffu, v, off);
        if (lane == 0) s_off = v;
    }
    __syncthreads();
    int i = b * 1024 + threadIdx.x;
    if (i < n) {
        int r = g_rowstart[i] + s_off;
        g_rowstart[i] = r;
        g_cursor[i] = r;
    }
    if (b == nb - 1 && threadIdx.x == 0)
        g_rowstart[n] = s_off + g_blocksums[b];
}

__global__ void fill_kernel(int E) {
    int e = blockIdx.x * blockDim.x + threadIdx.x;
    if (e >= E) return;
    int pos = atomicAdd(&g_cursor[g_dst[e]], 1);
    g_csr[pos] = g_src[e];
}

// ---------------- layer-1 aggregation: warp per node, fp16 gather + fp16 out ----------------
__global__ void agg1_kernel(int n) {
    int w = (blockIdx.x * blockDim.x + threadIdx.x) >> 5;
    int lane = threadIdx.x & 31;
    if (w >= n) return;
    int s0 = g_rowstart[w], s1 = g_rowstart[w + 1];
    float f0 = 0.f, f1 = 0.f, f2 = 0.f, f3 = 0.f;
    float f4 = 0.f, f5 = 0.f, f6 = 0.f, f7 = 0.f;
    for (int e = s0; e < s1; e++) {
        int s = g_csr[e];
        uint4 v = *(const uint4*)(g_xhalf + (size_t)s * C + 8 * lane);
        float2 p0 = __half22float2(*(__half2*)&v.x);
        float2 p1 = __half22float2(*(__half2*)&v.y);
        float2 p2 = __half22float2(*(__half2*)&v.z);
        float2 p3 = __half22float2(*(__half2*)&v.w);
        f0 += p0.x; f1 += p0.y; f2 += p1.x; f3 += p1.y;
        f4 += p2.x; f5 += p2.y; f6 += p3.x; f7 += p3.y;
    }
    float inv = (s1 > s0) ? 1.f / (float)(s1 - s0) : 0.f;
    f0 *= inv; f1 *= inv; f2 *= inv; f3 *= inv;
    f4 *= inv; f5 *= inv; f6 *= inv; f7 *= inv;
    *(uint4*)(g_agghalf + (size_t)w * C + 8 * lane) =
        make_uint4(packhf(f0, f1), packhf(f2, f3), packhf(f4, f5), packhf(f6, f7));
}

// ---------------- double-buffered fp16 mma GEMM + fused pq epilogue ----------------
// CTA: 128 rows x 256 cols, 512 threads, warp grid 4m x 4n, warp tile 32x64.
// D = A*Bh + A*Bl (A fp16, W split fp16 hi/lo), fp32 accum. K=512, 16 tiles of 32.
#define PA 40                        // smem pitch in halfs (80 bytes)
#define SA 0                         // 128*80 = 10240
#define SB_HI 10240                  // 256*80 = 20480
#define SB_LO 30720
#define STAGE 51200
#define SW2   102400                 // 256*16 = 4096
#define SB1   106496                 // 1024
#define SMEMT 107520

__global__ void __launch_bounds__(512, 1) gemm_mma_kernel(
    const float* __restrict__ b1, const float* __restrict__ b2, int M)
{
    extern __shared__ __align__(16) char smem[];
    u32 sb = smem_u32(smem);
    int tid = threadIdx.x;
    int lane = tid & 31, wid = tid >> 5;
    int wm = wid >> 2, wn = wid & 3;
    int m0 = blockIdx.x * 128;

    float4* s_w2 = (float4*)(smem + SW2);
    float*  s_b1 = (float*)(smem + SB1);
    if (tid < 256) {
        s_w2[tid] = g_W2pack[tid];
        s_b1[tid] = b1[tid];
    }

    // per-thread cp.async assignments: A = 512 x 16B chunks per stage
    int arow = tid >> 2, ach = tid & 3;
    int am = m0 + arow;
    u32 asz = (am < M) ? 16u : 0u;
    u32 a_soff = (u32)(arow * 80 + ach * 16);
    size_t a_goff = (size_t)am * C + ach * 8;

    auto issue = [&](int kt, int st) {
        u32 s0 = sb + st * STAGE;
        const __half* asrc = (kt < 8) ? g_agghalf : g_xhalf;
        size_t ago = a_goff + (size_t)(kt & 7) * 32;
        CP16(s0 + SA + a_soff, asrc + ago, asz);
        int kg = kt * 32;
        #pragma unroll
        for (int i = 0; i < 2; i++) {
            int t = tid + i * 512;
            int nr = t >> 2, ch = t & 3;
            u32 boff = (u32)(nr * 80 + ch * 16);
            size_t bgo = (size_t)nr * 512 + kg + ch * 8;
            CP16(s0 + SB_HI + boff, g_Whi + bgo, 16u);
            CP16(s0 + SB_LO + boff, g_Wlo + bgo, 16u);
        }
        CP_COMMIT();
    };

    float c[2][8][4];
    #pragma unroll
    for (int mi = 0; mi < 2; mi++)
        #pragma unroll
        for (int ni = 0; ni < 8; ni++)
            #pragma unroll
            for (int j = 0; j < 4; j++) c[mi][ni][j] = 0.f;

    int ra = lane >> 2;
    int ka2 = (lane & 3) * 2;

    issue(0, 0);
    for (int kt = 0; kt < 16; kt++) {
        if (kt < 15) { issue(kt + 1, (kt + 1) & 1); CP_WAIT(1); }
        else         { CP_WAIT(0); }
        __syncthreads();
        char* sB = smem + (kt & 1) * STAGE;
        #pragma unroll
        for (int k16 = 0; k16 < 2; k16++) {
            int k0 = k16 * 16;
            u32 a[2][4];
            #pragma unroll
            for (int mi = 0; mi < 2; mi++) {
                int base = ((32 * wm + 16 * mi + ra) * PA + k0 + ka2) * 2;
                a[mi][0] = *(u32*)(sB + SA + base);
                a[mi][1] = *(u32*)(sB + SA + base + 8 * PA * 2);
                a[mi][2] = *(u32*)(sB + SA + base + 16);
                a[mi][3] = *(u32*)(sB + SA + base + 8 * PA * 2 + 16);
            }
            u32 bh[8][2], bl[8][2];
            #pragma unroll
            for (int ni = 0; ni < 8; ni++) {
                int nb = 64 * wn + 8 * ni + ra;
                int boff = (nb * PA + k0 + ka2) * 2;
                bh[ni][0] = *(u32*)(sB + SB_HI + boff);
                bh[ni][1] = *(u32*)(sB + SB_HI + boff + 16);
                bl[ni][0] = *(u32*)(sB + SB_LO + boff);
                bl[ni][1] = *(u32*)(sB + SB_LO + boff + 16);
            }
            #pragma unroll
            for (int mi = 0; mi < 2; mi++)
                #pragma unroll
                for (int ni = 0; ni < 8; ni++) {
                    mma16816(c[mi][ni], a[mi], bh[ni]);
                    mma16816(c[mi][ni], a[mi], bl[ni]);
                }
        }
        __syncthreads();
    }

    // ---- epilogue: h = relu(acc + b1); fused p,q projection
    float pp[2][2][4];
    #pragma unroll
    for (int mi = 0; mi < 2; mi++)
        #pragma unroll
        for (int hh = 0; hh < 2; hh++)
            #pragma unroll
            for (int r = 0; r < 4; r++) pp[mi][hh][r] = 0.f;
    #pragma unroll
    for (int mi = 0; mi < 2; mi++)
        #pragma unroll
        for (int ni = 0; ni < 8; ni++)
            #pragma unroll
            for (int j = 0; j < 4; j++) {
                int col = 64 * wn + 8 * ni + ka2 + (j & 1);
                float h = fmaxf(c[mi][ni][j] + s_b1[col], 0.f);
                float4 wv = s_w2[col];
                int hh = j >> 1;
                pp[mi][hh][0] = fmaf(h, wv.x, pp[mi][hh][0]);
                pp[mi][hh][1] = fmaf(h, wv.y, pp[mi][hh][1]);
                pp[mi][hh][2] = fmaf(h, wv.z, pp[mi][hh][2]);
                pp[mi][hh][3] = fmaf(h, wv.w, pp[mi][hh][3]);
            }
    #pragma unroll
    for (int mi = 0; mi < 2; mi++)
        #pragma unroll
        for (int hh = 0; hh < 2; hh++)
            #pragma unroll
            for (int r = 0; r < 4; r++) {
                float v = pp[mi][hh][r];
                v += __shfl_xor_sync(0xffffffffu, v, 1);
                v += __shfl_xor_sync(0xffffffffu, v, 2);
                pp[mi][hh][r] = v;
            }
    float* s_part = (float*)smem;   // [4 wn][128 row][4]
    if ((lane & 3) == 0) {
        #pragma unroll
        for (int mi = 0; mi < 2; mi++)
            #pragma unroll
            for (int hh = 0; hh < 2; hh++) {
                int row = 32 * wm + 16 * mi + 8 * hh + ra;
                *(float4*)&s_part[(wn * 128 + row) * 4] =
                    make_float4(pp[mi][hh][0], pp[mi][hh][1], pp[mi][hh][2], pp[mi][hh][3]);
            }
    }
    __syncthreads();
    if (tid < 128) {
        int m = m0 + tid;
        if (m < M) {
            float4 s = make_float4(0.f, 0.f, 0.f, 0.f);
            #pragma unroll
            for (int w = 0; w < 4; w++) {
                float4 v = *(float4*)&s_part[(w * 128 + tid) * 4];
                s.x += v.x; s.y += v.y; s.z += v.z; s.w += v.w;
            }
            *(float4*)&g_pq[m * 4] = make_float4(s.x, s.y, s.z + b2[0], s.w + b2[1]);
        }
    }
}

// ---------------- layer-2 aggregation + log_softmax ----------------
__global__ void final_kernel(float* __restrict__ out, int n) {
    int i = blockIdx.x * blockDim.x + threadIdx.x;
    if (i >= n) return;
    int s0 = g_rowstart[i], s1 = g_rowstart[i + 1];
    float p0 = 0.f, p1 = 0.f;
    for (int e = s0; e < s1; e++) {
        int s = g_csr[e];
        p0 += g_pq[s * 4 + 0];
        p1 += g_pq[s * 4 + 1];
    }
    float inv = (s1 > s0) ? 1.f / (float)(s1 - s0) : 0.f;
    float o0 = p0 * inv + g_pq[i * 4 + 2];
    float o1 = p1 * inv + g_pq[i * 4 + 3];
    float m = fmaxf(o0, o1);
    float l = m + log1pf(expf(fminf(o0, o1) - m));
    out[i * 2 + 0] = o0 - l;
    out[i * 2 + 1] = o1 - l;
}

// ---------------- launcher ----------------
extern "C" void kernel_launch(void* const* d_in, const int* in_sizes, int n_in,
                              void* d_out, int out_size) {
    const float* x   = (const float*)d_in[0];
    const int*   ei  = (const int*)d_in[1];
    const float* W1l = (const float*)d_in[2];
    const float* b1  = (const float*)d_in[3];
    const float* W1r = (const float*)d_in[4];
    const float* W2l = (const float*)d_in[5];
    const float* b2  = (const float*)d_in[6];
    const float* W2r = (const float*)d_in[7];
    float* out = (float*)d_out;

    int n = in_sizes[0] / C;  if (n > NMAX) n = NMAX;
    int E = in_sizes[1] / 2;  if (E > EMAX) E = EMAX;
    int nb = (n + 1023) / 1024;
    int nbx = (n * 64 + 255) / 256;
    int nbc = (E + 255) / 256;

    cudaFuncSetAttribute(gemm_mma_kernel, cudaFuncAttributeMaxDynamicSharedMemorySize,
                         SMEMT);

    init_kernel<<<(n + 255) / 256, 256>>>((const unsigned*)ei, n);
    prep_kernel<<<nbx + nbc + 512, 256>>>(x, ei, W1l, W1r, W2l, W2r, n, E, nbx, nbc);
    scan_block_kernel<<<nb, 1024>>>(n);
    scan_add_kernel<<<nb, 1024>>>(n, nb);
    fill_kernel<<<(E + 255) / 256, 256>>>(E);
    agg1_kernel<<<(n * 32 + 255) / 256, 256>>>(n);
    gemm_mma_kernel<<<(n + 127) / 128, 512, SMEMT>>>(b1, b2, n);
    final_kernel<<<(n + 255) / 256, 256>>>(out, n);
}